// round 3
// baseline (speedup 1.0000x reference)
#include <cuda_runtime.h>
#include <cstdint>

#define NCTA 128
#define NTHR 256
static constexpr int Bn = 32, Tn = 64, Sn = 128, Hn = 512, En = 512, Vn = 32000;
static constexpr float NEGV = -1e4f;

// ---------------- device scratch (allocation-free) ----------------
__device__ float g_xT[Tn][En][Bn];
__device__ float g_feedT[Hn][Bn];
__device__ float g_h0T[2][Hn][Bn];
__device__ float g_h1T[2][Hn][Bn];
__device__ float g_qT[Hn][Bn];
__device__ float g_ctxT[Hn][Bn];
__device__ float g_dec[Bn * Tn][Hn];
__device__ float g_tmp[Bn * Tn][En];
__device__ unsigned g_count;
__device__ volatile unsigned g_gen;

// ---------------- grid barrier (all 128 CTAs co-resident) ----------------
__device__ __forceinline__ void gbar()
{
    __threadfence();
    __syncthreads();
    if (threadIdx.x == 0) {
        unsigned g = g_gen;
        unsigned a = atomicAdd(&g_count, 1u);
        if (a == NCTA - 1u) {
            g_count = 0u;
            __threadfence();
            g_gen = g + 1u;
        } else {
            while (g_gen == g) { }
        }
    }
    __syncthreads();
    __threadfence();
}

__device__ __forceinline__ float sigm(float x) { return 1.f / (1.f + __expf(-x)); }

// 4 weight rows (ldg) vs transposed activations [k][32] (ldcg)
__device__ __forceinline__ void dot4(const float* __restrict__ w0, const float* __restrict__ w1,
                                     const float* __restrict__ w2, const float* __restrict__ w3,
                                     const float* __restrict__ act, int lane, int n, float acc[4])
{
#pragma unroll 2
    for (int k = 0; k < n; k += 4) {
        const float* a = act + k * Bn + lane;
        float i0 = __ldcg(a), i1 = __ldcg(a + Bn), i2 = __ldcg(a + 2 * Bn), i3 = __ldcg(a + 3 * Bn);
        float4 w;
        w = __ldg((const float4*)(w0 + k)); acc[0] += w.x * i0 + w.y * i1 + w.z * i2 + w.w * i3;
        w = __ldg((const float4*)(w1 + k)); acc[1] += w.x * i0 + w.y * i1 + w.z * i2 + w.w * i3;
        w = __ldg((const float4*)(w2 + k)); acc[2] += w.x * i0 + w.y * i1 + w.z * i2 + w.w * i3;
        w = __ldg((const float4*)(w3 + k)); acc[3] += w.x * i0 + w.y * i1 + w.z * i2 + w.w * i3;
    }
}

__device__ __forceinline__ float dot1(const float* __restrict__ w,
                                      const float* __restrict__ act, int lane, int n)
{
    float acc = 0.f;
#pragma unroll 2
    for (int k = 0; k < n; k += 4) {
        const float* a = act + k * Bn + lane;
        float i0 = __ldcg(a), i1 = __ldcg(a + Bn), i2 = __ldcg(a + 2 * Bn), i3 = __ldcg(a + 3 * Bn);
        float4 w4 = __ldg((const float4*)(w + k));
        acc += w4.x * i0 + w4.y * i1 + w4.z * i2 + w4.w * i3;
    }
    return acc;
}

// ---------------- persistent recurrence ----------------
__global__ void __launch_bounds__(NTHR, 1)
recurrent_kernel(const int* __restrict__ tokens, const float* __restrict__ enc,
                 const int* __restrict__ mask, const float* __restrict__ embed,
                 const float* __restrict__ w_ih0, const float* __restrict__ w_hh0,
                 const float* __restrict__ b_ih0, const float* __restrict__ b_hh0,
                 const float* __restrict__ w_ih1, const float* __restrict__ w_hh1,
                 const float* __restrict__ b_ih1, const float* __restrict__ b_hh1,
                 const float* __restrict__ attn_in_w, const float* __restrict__ attn_out_w)
{
    const int tid = threadIdx.x, cta = blockIdx.x;
    const int warp = tid >> 5, lane = tid & 31;
    const int gtid = cta * NTHR + tid;

    __shared__ __align__(16) float part[4][4][32];
    __shared__ __align__(16) float s_q[512];
    __shared__ float s_sc[128];
    __shared__ float s_red[32];

    // ---- per-launch init: zero recurrent state ----
    for (int i = gtid; i < Hn * Bn; i += NCTA * NTHR) {
        (&g_feedT[0][0])[i] = 0.f;
        (&g_h0T[0][0][0])[i] = 0.f; (&g_h0T[1][0][0])[i] = 0.f;
        (&g_h1T[0][0][0])[i] = 0.f; (&g_h1T[1][0][0])[i] = 0.f;
    }
    // ---- embed gather+transpose ----
    {
        int gw = gtid >> 5;                 // 1024 warps, 2 (t,b) pairs each
#pragma unroll
        for (int rep = 0; rep < 2; rep++) {
            int p = gw * 2 + rep;
            int b = p & 31, t0 = p >> 5;
            int tok = __ldg(tokens + b * Tn + t0);
            const float4* er = (const float4*)(embed + (size_t)tok * En);
#pragma unroll
            for (int i = 0; i < 4; i++) {
                float4 v = __ldg(er + i * 32 + lane);
                int e = (i * 32 + lane) * 4;
                g_xT[t0][e][b] = v.x; g_xT[t0][e + 1][b] = v.y;
                g_xT[t0][e + 2][b] = v.z; g_xT[t0][e + 3][b] = v.w;
            }
        }
    }
    gbar();

    const int jl = warp >> 1, kh = warp & 1, j = cta * 4 + jl;
    float c0r = 0.f, c1r = 0.f;

    for (int t = 0; t < Tn; t++) {
        const int cur = t & 1, prv = cur ^ 1;

        // ---------- Phase A: LSTM layer 0 ----------
        {
            float acc[4] = {0.f, 0.f, 0.f, 0.f};
            const size_t r0 = (size_t)j * 1024, r1 = (size_t)(j + 512) * 1024,
                         r2 = (size_t)(j + 1024) * 1024, r3 = (size_t)(j + 1536) * 1024;
            if (kh == 0) {
                dot4(w_ih0 + r0, w_ih0 + r1, w_ih0 + r2, w_ih0 + r3,
                     &g_xT[t][0][0], lane, 512, acc);
                dot4(w_ih0 + r0 + 512, w_ih0 + r1 + 512, w_ih0 + r2 + 512, w_ih0 + r3 + 512,
                     &g_feedT[0][0], lane, 256, acc);
            } else {
                dot4(w_ih0 + r0 + 768, w_ih0 + r1 + 768, w_ih0 + r2 + 768, w_ih0 + r3 + 768,
                     &g_feedT[256][0], lane, 256, acc);
                const size_t h0 = (size_t)j * 512, h1 = (size_t)(j + 512) * 512,
                             h2 = (size_t)(j + 1024) * 512, h3 = (size_t)(j + 1536) * 512;
                dot4(w_hh0 + h0, w_hh0 + h1, w_hh0 + h2, w_hh0 + h3,
                     &g_h0T[prv][0][0], lane, 512, acc);
                part[jl][0][lane] = acc[0]; part[jl][1][lane] = acc[1];
                part[jl][2][lane] = acc[2]; part[jl][3][lane] = acc[3];
            }
            __syncthreads();
            if (kh == 0) {
                float gi = acc[0] + part[jl][0][lane] + __ldg(b_ih0 + j)        + __ldg(b_hh0 + j);
                float gf = acc[1] + part[jl][1][lane] + __ldg(b_ih0 + j + 512)  + __ldg(b_hh0 + j + 512);
                float gg = acc[2] + part[jl][2][lane] + __ldg(b_ih0 + j + 1024) + __ldg(b_hh0 + j + 1024);
                float go = acc[3] + part[jl][3][lane] + __ldg(b_ih0 + j + 1536) + __ldg(b_hh0 + j + 1536);
                c0r = sigm(gf) * c0r + sigm(gi) * tanhf(gg);
                g_h0T[cur][j][lane] = sigm(go) * tanhf(c0r);
            }
        }
        gbar();

        // ---------- Phase B: LSTM layer 1 ----------
        {
            float acc[4] = {0.f, 0.f, 0.f, 0.f};
            const size_t r0 = (size_t)j * 512, r1 = (size_t)(j + 512) * 512,
                         r2 = (size_t)(j + 1024) * 512, r3 = (size_t)(j + 1536) * 512;
            if (kh == 0) {
                dot4(w_ih1 + r0, w_ih1 + r1, w_ih1 + r2, w_ih1 + r3,
                     &g_h0T[cur][0][0], lane, 512, acc);
            } else {
                dot4(w_hh1 + r0, w_hh1 + r1, w_hh1 + r2, w_hh1 + r3,
                     &g_h1T[prv][0][0], lane, 512, acc);
                part[jl][0][lane] = acc[0]; part[jl][1][lane] = acc[1];
                part[jl][2][lane] = acc[2]; part[jl][3][lane] = acc[3];
            }
            __syncthreads();
            if (kh == 0) {
                float gi = acc[0] + part[jl][0][lane] + __ldg(b_ih1 + j)        + __ldg(b_hh1 + j);
                float gf = acc[1] + part[jl][1][lane] + __ldg(b_ih1 + j + 512)  + __ldg(b_hh1 + j + 512);
                float gg = acc[2] + part[jl][2][lane] + __ldg(b_ih1 + j + 1024) + __ldg(b_hh1 + j + 1024);
                float go = acc[3] + part[jl][3][lane] + __ldg(b_ih1 + j + 1536) + __ldg(b_hh1 + j + 1536);
                c1r = sigm(gf) * c1r + sigm(gi) * tanhf(gg);
                g_h1T[cur][j][lane] = sigm(go) * tanhf(c1r);
            }
        }
        gbar();

        // ---------- Phase C: q = attn_in_w @ h1 ----------
        {
            float a = dot1(attn_in_w + (size_t)j * 512 + kh * 256,
                           &g_h1T[cur][kh * 256][0], lane, 256);
            if (kh == 1) part[jl][0][lane] = a;
            __syncthreads();
            if (kh == 0) g_qT[j][lane] = a + part[jl][0][lane];
        }
        gbar();

        // ---------- Phase D: scores -> softmax -> ctx (one CTA per batch) ----------
        if (cta < Bn) {
            const int b = cta;
            for (int k = tid; k < 512; k += NTHR) s_q[k] = __ldcg(&g_qT[k][b]);
            __syncthreads();
            for (int i = 0; i < 16; i++) {
                int sp = warp * 16 + i;
                const float4* er = (const float4*)(enc + ((size_t)b * Sn + sp) * Hn);
                const float4* qr = (const float4*)s_q;
                float acc = 0.f;
#pragma unroll
                for (int c4 = 0; c4 < 4; c4++) {
                    float4 e = __ldg(er + c4 * 32 + lane);
                    float4 q4 = qr[c4 * 32 + lane];
                    acc += e.x * q4.x + e.y * q4.y + e.z * q4.z + e.w * q4.w;
                }
#pragma unroll
                for (int o = 16; o; o >>= 1) acc += __shfl_xor_sync(~0u, acc, o);
                if (lane == 0)
                    s_sc[sp] = (__ldg(mask + b * Sn + sp) == 0) ? NEGV : acc;
            }
            __syncthreads();
            // softmax over 128
            float mv = (tid < 128) ? s_sc[tid] : -3e38f;
#pragma unroll
            for (int o = 16; o; o >>= 1) mv = fmaxf(mv, __shfl_xor_sync(~0u, mv, o));
            if (lane == 0) s_red[warp] = mv;
            __syncthreads();
            if (tid == 0) {
                float m = s_red[0];
                for (int w = 1; w < 8; w++) m = fmaxf(m, s_red[w]);
                s_red[16] = m;
            }
            __syncthreads();
            float ev = 0.f;
            if (tid < 128) ev = __expf(s_sc[tid] - s_red[16]);
            float sv = ev;
#pragma unroll
            for (int o = 16; o; o >>= 1) sv += __shfl_xor_sync(~0u, sv, o);
            if (lane == 0) s_red[warp] = sv;
            __syncthreads();
            if (tid == 0) {
                float s = 0.f;
                for (int w = 0; w < 8; w++) s += s_red[w];
                s_red[17] = 1.f / s;
            }
            __syncthreads();
            if (tid < 128) s_sc[tid] = ev * s_red[17];
            __syncthreads();
            // ctx
#pragma unroll
            for (int rep = 0; rep < 2; rep++) {
                int h = tid + rep * 256;
                const float* ep = enc + (size_t)b * Sn * Hn + h;
                float acc = 0.f;
#pragma unroll 4
                for (int s = 0; s < Sn; s++) acc += s_sc[s] * __ldg(ep + s * Hn);
                g_ctxT[h][b] = acc;
            }
        }
        gbar();

        // ---------- Phase E: input_feed = tanh(attn_out_w @ [ctx; h1]) ----------
        {
            const float* wr = attn_out_w + (size_t)j * 1024 + kh * 512;
            float a = dot1(wr, kh == 0 ? &g_ctxT[0][0] : &g_h1T[cur][0][0], lane, 512);
            if (kh == 1) part[jl][0][lane] = a;
            __syncthreads();
            if (kh == 0) {
                float f = tanhf(a + part[jl][0][lane]);
                g_feedT[j][lane] = f;
                g_dec[lane * Tn + t][j] = f;
            }
        }
        gbar();
    }
}

// ---------------- FFMA2 helpers ----------------
__device__ __forceinline__ unsigned long long pack2(float x)
{
    unsigned long long r;
    asm("mov.b64 %0, {%1, %1};" : "=l"(r) : "f"(x));
    return r;
}
__device__ __forceinline__ void ffma2(unsigned long long& d, unsigned long long a, unsigned long long b)
{
    asm("fma.rn.f32x2 %0, %1, %2, %0;" : "+l"(d) : "l"(a), "l"(b));
}
__device__ __forceinline__ float2 unpack2(unsigned long long v)
{
    float2 r;
    asm("mov.b64 {%0, %1}, %2;" : "=f"(r.x), "=f"(r.y) : "l"(v));
    return r;
}

// ---------------- C = A @ W^T (+bias), 128x128 tiles, 8x8/thread, f32x2 ----------------
__global__ void __launch_bounds__(256)
gemm_nt(const float* __restrict__ A, const float* __restrict__ W,
        const float* __restrict__ bias, float* __restrict__ C,
        int M, int N, int K)
{
    __shared__ __align__(16) float As[16][128];
    __shared__ __align__(16) float Ws[16][128];
    const int m0 = blockIdx.y * 128, n0 = blockIdx.x * 128;
    const int tid = threadIdx.x;
    const int tx = tid & 15, ty = tid >> 4;
    const int lrow = tid >> 1, lcol = (tid & 1) * 8;

    unsigned long long acc2[8][4];
#pragma unroll
    for (int i = 0; i < 8; i++)
#pragma unroll
        for (int jj = 0; jj < 4; jj++) acc2[i][jj] = 0ull;

    const float* Aload = A + (size_t)(m0 + lrow) * K + lcol;
    const float* Wload = W + (size_t)(n0 + lrow) * K + lcol;

    for (int k0 = 0; k0 < K; k0 += 16) {
        float4 a0 = __ldg((const float4*)(Aload + k0));
        float4 a1 = __ldg((const float4*)(Aload + k0 + 4));
        float4 w0 = __ldg((const float4*)(Wload + k0));
        float4 w1 = __ldg((const float4*)(Wload + k0 + 4));
        __syncthreads();
        As[lcol + 0][lrow] = a0.x; As[lcol + 1][lrow] = a0.y;
        As[lcol + 2][lrow] = a0.z; As[lcol + 3][lrow] = a0.w;
        As[lcol + 4][lrow] = a1.x; As[lcol + 5][lrow] = a1.y;
        As[lcol + 6][lrow] = a1.z; As[lcol + 7][lrow] = a1.w;
        Ws[lcol + 0][lrow] = w0.x; Ws[lcol + 1][lrow] = w0.y;
        Ws[lcol + 2][lrow] = w0.z; Ws[lcol + 3][lrow] = w0.w;
        Ws[lcol + 4][lrow] = w1.x; Ws[lcol + 5][lrow] = w1.y;
        Ws[lcol + 6][lrow] = w1.z; Ws[lcol + 7][lrow] = w1.w;
        __syncthreads();
#pragma unroll
        for (int kk = 0; kk < 16; kk++) {
            float4 av0 = *(const float4*)&As[kk][ty * 8];
            float4 av1 = *(const float4*)&As[kk][ty * 8 + 4];
            const ulonglong2* wp = (const ulonglong2*)&Ws[kk][tx * 8];
            ulonglong2 b01 = wp[0], b23 = wp[1];
            float a8[8] = {av0.x, av0.y, av0.z, av0.w, av1.x, av1.y, av1.z, av1.w};
#pragma unroll
            for (int i = 0; i < 8; i++) {
                unsigned long long a2 = pack2(a8[i]);
                ffma2(acc2[i][0], a2, b01.x);
                ffma2(acc2[i][1], a2, b01.y);
                ffma2(acc2[i][2], a2, b23.x);
                ffma2(acc2[i][3], a2, b23.y);
            }
        }
    }

#pragma unroll
    for (int i = 0; i < 8; i++) {
        float* Crow = C + (size_t)(m0 + ty * 8 + i) * N + n0 + tx * 8;
#pragma unroll
        for (int jj = 0; jj < 4; jj++) {
            float2 v = unpack2(acc2[i][jj]);
            if (bias) {
                v.x += __ldg(bias + n0 + tx * 8 + 2 * jj);
                v.y += __ldg(bias + n0 + tx * 8 + 2 * jj + 1);
            }
            *(float2*)(Crow + 2 * jj) = v;
        }
    }
}

extern "C" void kernel_launch(void* const* d_in, const int* in_sizes, int n_in,
                              void* d_out, int out_size)
{
    const int*   tokens     = (const int*)d_in[0];
    const float* enc        = (const float*)d_in[1];
    const int*   mask       = (const int*)d_in[2];
    const float* embed      = (const float*)d_in[3];
    const float* w_ih0      = (const float*)d_in[4];
    const float* w_hh0      = (const float*)d_in[5];
    const float* b_ih0      = (const float*)d_in[6];
    const float* b_hh0      = (const float*)d_in[7];
    const float* w_ih1      = (const float*)d_in[8];
    const float* w_hh1      = (const float*)d_in[9];
    const float* b_ih1      = (const float*)d_in[10];
    const float* b_hh1      = (const float*)d_in[11];
    const float* attn_in_w  = (const float*)d_in[12];
    const float* attn_out_w = (const float*)d_in[13];
    const float* out_proj_w = (const float*)d_in[14];
    const float* out_proj_b = (const float*)d_in[15];
    float* out = (float*)d_out;

    float *dec, *tmp;
    cudaGetSymbolAddress((void**)&dec, g_dec);
    cudaGetSymbolAddress((void**)&tmp, g_tmp);

    recurrent_kernel<<<NCTA, NTHR>>>(tokens, enc, mask, embed,
                                     w_ih0, w_hh0, b_ih0, b_hh0,
                                     w_ih1, w_hh1, b_ih1, b_hh1,
                                     attn_in_w, attn_out_w);
    gemm_nt<<<dim3(En / 128, (Bn * Tn) / 128), 256>>>(dec, out_proj_w, out_proj_b, tmp,
                                                      Bn * Tn, En, Hn);
    gemm_nt<<<dim3(Vn / 128, (Bn * Tn) / 128), 256>>>(tmp, embed, nullptr, out,
                                                      Bn * Tn, Vn, En);
}

// round 5
// speedup vs baseline: 1.0884x; 1.0884x over previous
#include <cuda_runtime.h>
#include <cuda_bf16.h>
#include <cstdint>

#define NCTA 128
#define NTHR 256
static constexpr int Bn = 32, Tn = 64, Sn = 128, Hn = 512, En = 512, Vn = 32000;
static constexpr float NEGV = -1e4f;

// ---------------- device scratch (allocation-free) ----------------
__device__ float g_xT[Tn][En][Bn];
__device__ float g_feedT[Hn][Bn];
__device__ float g_h0T[2][Hn][Bn];
__device__ float g_h1T[2][Hn][Bn];
__device__ float g_qT[Hn][Bn];
__device__ float g_ctxT[Hn][Bn];
__device__ float g_dec[Bn * Tn][Hn];
__device__ float g_tmp[Bn * Tn][En];
__device__ __nv_bfloat16 g_Ahi[Bn * Tn * En];
__device__ __nv_bfloat16 g_Alo[Bn * Tn * En];
__device__ __nv_bfloat16 g_Bhi[Vn * En];
__device__ __nv_bfloat16 g_Blo[Vn * En];
__device__ unsigned g_count;
__device__ volatile unsigned g_gen;

// ---------------- grid barrier (all 128 CTAs co-resident) ----------------
// __threadfence() is gpu-scope => ptxas emits CCTL.IVALL => L1D flushed.
// Therefore post-barrier L1-cached loads (__ldca) of cross-CTA data are safe.
__device__ __forceinline__ void gbar()
{
    __threadfence();
    __syncthreads();
    if (threadIdx.x == 0) {
        unsigned g = g_gen;
        unsigned a = atomicAdd(&g_count, 1u);
        if (a == NCTA - 1u) {
            g_count = 0u;
            __threadfence();
            g_gen = g + 1u;
        } else {
            while (g_gen == g) { }
        }
    }
    __syncthreads();
    __threadfence();
}

__device__ __forceinline__ float sigm(float x) { return 1.f / (1.f + __expf(-x)); }

// 4 weight rows (ldg, immutable) vs transposed activations [k][32] (ldca: L1-cached,
// coherent because every gbar flushes L1)
__device__ __forceinline__ void dot4(const float* __restrict__ w0, const float* __restrict__ w1,
                                     const float* __restrict__ w2, const float* __restrict__ w3,
                                     const float* __restrict__ act, int lane, int n, float acc[4])
{
#pragma unroll 2
    for (int k = 0; k < n; k += 4) {
        const float* a = act + k * Bn + lane;
        float i0 = __ldca(a), i1 = __ldca(a + Bn), i2 = __ldca(a + 2 * Bn), i3 = __ldca(a + 3 * Bn);
        float4 w;
        w = __ldg((const float4*)(w0 + k)); acc[0] += w.x * i0 + w.y * i1 + w.z * i2 + w.w * i3;
        w = __ldg((const float4*)(w1 + k)); acc[1] += w.x * i0 + w.y * i1 + w.z * i2 + w.w * i3;
        w = __ldg((const float4*)(w2 + k)); acc[2] += w.x * i0 + w.y * i1 + w.z * i2 + w.w * i3;
        w = __ldg((const float4*)(w3 + k)); acc[3] += w.x * i0 + w.y * i1 + w.z * i2 + w.w * i3;
    }
}

__device__ __forceinline__ float dot1(const float* __restrict__ w,
                                      const float* __restrict__ act, int lane, int n)
{
    float acc = 0.f;
#pragma unroll 2
    for (int k = 0; k < n; k += 4) {
        const float* a = act + k * Bn + lane;
        float i0 = __ldca(a), i1 = __ldca(a + Bn), i2 = __ldca(a + 2 * Bn), i3 = __ldca(a + 3 * Bn);
        float4 w4 = __ldg((const float4*)(w + k));
        acc += w4.x * i0 + w4.y * i1 + w4.z * i2 + w4.w * i3;
    }
    return acc;
}

// ---------------- persistent recurrence ----------------
__global__ void __launch_bounds__(NTHR, 1)
recurrent_kernel(const int* __restrict__ tokens, const float* __restrict__ enc,
                 const int* __restrict__ mask, const float* __restrict__ embed,
                 const float* __restrict__ w_ih0, const float* __restrict__ w_hh0,
                 const float* __restrict__ b_ih0, const float* __restrict__ b_hh0,
                 const float* __restrict__ w_ih1, const float* __restrict__ w_hh1,
                 const float* __restrict__ b_ih1, const float* __restrict__ b_hh1,
                 const float* __restrict__ attn_in_w, const float* __restrict__ attn_out_w)
{
    const int tid = threadIdx.x, cta = blockIdx.x;
    const int warp = tid >> 5, lane = tid & 31;
    const int gtid = cta * NTHR + tid;

    __shared__ __align__(16) float part[4][4][32];
    __shared__ __align__(16) float s_q[512];
    __shared__ float s_sc[128];
    __shared__ float s_red[32];

    for (int i = gtid; i < Hn * Bn; i += NCTA * NTHR) {
        (&g_feedT[0][0])[i] = 0.f;
        (&g_h0T[0][0][0])[i] = 0.f; (&g_h0T[1][0][0])[i] = 0.f;
        (&g_h1T[0][0][0])[i] = 0.f; (&g_h1T[1][0][0])[i] = 0.f;
    }
    {
        int gw = gtid >> 5;
#pragma unroll
        for (int rep = 0; rep < 2; rep++) {
            int p = gw * 2 + rep;
            int b = p & 31, t0 = p >> 5;
            int tok = __ldg(tokens + b * Tn + t0);
            const float4* er = (const float4*)(embed + (size_t)tok * En);
#pragma unroll
            for (int i = 0; i < 4; i++) {
                float4 v = __ldg(er + i * 32 + lane);
                int e = (i * 32 + lane) * 4;
                g_xT[t0][e][b] = v.x; g_xT[t0][e + 1][b] = v.y;
                g_xT[t0][e + 2][b] = v.z; g_xT[t0][e + 3][b] = v.w;
            }
        }
    }
    gbar();

    const int jl = warp >> 1, kh = warp & 1, j = cta * 4 + jl;
    float c0r = 0.f, c1r = 0.f;

    for (int t = 0; t < Tn; t++) {
        const int cur = t & 1, prv = cur ^ 1;

        // ---------- Phase A: LSTM layer 0 ----------
        {
            float acc[4] = {0.f, 0.f, 0.f, 0.f};
            const size_t r0 = (size_t)j * 1024, r1 = (size_t)(j + 512) * 1024,
                         r2 = (size_t)(j + 1024) * 1024, r3 = (size_t)(j + 1536) * 1024;
            if (kh == 0) {
                dot4(w_ih0 + r0, w_ih0 + r1, w_ih0 + r2, w_ih0 + r3,
                     &g_xT[t][0][0], lane, 512, acc);
                dot4(w_ih0 + r0 + 512, w_ih0 + r1 + 512, w_ih0 + r2 + 512, w_ih0 + r3 + 512,
                     &g_feedT[0][0], lane, 256, acc);
            } else {
                dot4(w_ih0 + r0 + 768, w_ih0 + r1 + 768, w_ih0 + r2 + 768, w_ih0 + r3 + 768,
                     &g_feedT[256][0], lane, 256, acc);
                const size_t h0 = (size_t)j * 512, h1 = (size_t)(j + 512) * 512,
                             h2 = (size_t)(j + 1024) * 512, h3 = (size_t)(j + 1536) * 512;
                dot4(w_hh0 + h0, w_hh0 + h1, w_hh0 + h2, w_hh0 + h3,
                     &g_h0T[prv][0][0], lane, 512, acc);
                part[jl][0][lane] = acc[0]; part[jl][1][lane] = acc[1];
                part[jl][2][lane] = acc[2]; part[jl][3][lane] = acc[3];
            }
            __syncthreads();
            if (kh == 0) {
                float gi = acc[0] + part[jl][0][lane] + __ldg(b_ih0 + j)        + __ldg(b_hh0 + j);
                float gf = acc[1] + part[jl][1][lane] + __ldg(b_ih0 + j + 512)  + __ldg(b_hh0 + j + 512);
                float gg = acc[2] + part[jl][2][lane] + __ldg(b_ih0 + j + 1024) + __ldg(b_hh0 + j + 1024);
                float go = acc[3] + part[jl][3][lane] + __ldg(b_ih0 + j + 1536) + __ldg(b_hh0 + j + 1536);
                c0r = sigm(gf) * c0r + sigm(gi) * tanhf(gg);
                g_h0T[cur][j][lane] = sigm(go) * tanhf(c0r);
            }
        }
        gbar();

        // ---------- Phase B: LSTM layer 1 ----------
        {
            float acc[4] = {0.f, 0.f, 0.f, 0.f};
            const size_t r0 = (size_t)j * 512, r1 = (size_t)(j + 512) * 512,
                         r2 = (size_t)(j + 1024) * 512, r3 = (size_t)(j + 1536) * 512;
            if (kh == 0) {
                dot4(w_ih1 + r0, w_ih1 + r1, w_ih1 + r2, w_ih1 + r3,
                     &g_h0T[cur][0][0], lane, 512, acc);
            } else {
                dot4(w_hh1 + r0, w_hh1 + r1, w_hh1 + r2, w_hh1 + r3,
                     &g_h1T[prv][0][0], lane, 512, acc);
                part[jl][0][lane] = acc[0]; part[jl][1][lane] = acc[1];
                part[jl][2][lane] = acc[2]; part[jl][3][lane] = acc[3];
            }
            __syncthreads();
            if (kh == 0) {
                float gi = acc[0] + part[jl][0][lane] + __ldg(b_ih1 + j)        + __ldg(b_hh1 + j);
                float gf = acc[1] + part[jl][1][lane] + __ldg(b_ih1 + j + 512)  + __ldg(b_hh1 + j + 512);
                float gg = acc[2] + part[jl][2][lane] + __ldg(b_ih1 + j + 1024) + __ldg(b_hh1 + j + 1024);
                float go = acc[3] + part[jl][3][lane] + __ldg(b_ih1 + j + 1536) + __ldg(b_hh1 + j + 1536);
                c1r = sigm(gf) * c1r + sigm(gi) * tanhf(gg);
                g_h1T[cur][j][lane] = sigm(go) * tanhf(c1r);
            }
        }
        gbar();

        // ---------- Phase C: q = attn_in_w @ h1 ----------
        {
            float a = dot1(attn_in_w + (size_t)j * 512 + kh * 256,
                           &g_h1T[cur][kh * 256][0], lane, 256);
            if (kh == 1) part[jl][0][lane] = a;
            __syncthreads();
            if (kh == 0) g_qT[j][lane] = a + part[jl][0][lane];
        }
        gbar();

        // ---------- Phase D: scores -> softmax -> ctx (one CTA per batch) ----------
        if (cta < Bn) {
            const int b = cta;
            for (int k = tid; k < 512; k += NTHR) s_q[k] = __ldca(&g_qT[k][b]);
            __syncthreads();
            for (int i = 0; i < 16; i++) {
                int sp = warp * 16 + i;
                const float4* er = (const float4*)(enc + ((size_t)b * Sn + sp) * Hn);
                const float4* qr = (const float4*)s_q;
                float acc = 0.f;
#pragma unroll
                for (int c4 = 0; c4 < 4; c4++) {
                    float4 e = __ldg(er + c4 * 32 + lane);
                    float4 q4 = qr[c4 * 32 + lane];
                    acc += e.x * q4.x + e.y * q4.y + e.z * q4.z + e.w * q4.w;
                }
#pragma unroll
                for (int o = 16; o; o >>= 1) acc += __shfl_xor_sync(~0u, acc, o);
                if (lane == 0)
                    s_sc[sp] = (__ldg(mask + b * Sn + sp) == 0) ? NEGV : acc;
            }
            __syncthreads();
            float mv = (tid < 128) ? s_sc[tid] : -3e38f;
#pragma unroll
            for (int o = 16; o; o >>= 1) mv = fmaxf(mv, __shfl_xor_sync(~0u, mv, o));
            if (lane == 0) s_red[warp] = mv;
            __syncthreads();
            if (tid == 0) {
                float m = s_red[0];
                for (int w = 1; w < 8; w++) m = fmaxf(m, s_red[w]);
                s_red[16] = m;
            }
            __syncthreads();
            float ev = 0.f;
            if (tid < 128) ev = __expf(s_sc[tid] - s_red[16]);
            float sv = ev;
#pragma unroll
            for (int o = 16; o; o >>= 1) sv += __shfl_xor_sync(~0u, sv, o);
            if (lane == 0) s_red[warp] = sv;
            __syncthreads();
            if (tid == 0) {
                float s = 0.f;
                for (int w = 0; w < 8; w++) s += s_red[w];
                s_red[17] = 1.f / s;
            }
            __syncthreads();
            if (tid < 128) s_sc[tid] = ev * s_red[17];
            __syncthreads();
#pragma unroll
            for (int rep = 0; rep < 2; rep++) {
                int h = tid + rep * 256;
                const float* ep = enc + (size_t)b * Sn * Hn + h;
                float acc = 0.f;
#pragma unroll 4
                for (int s = 0; s < Sn; s++) acc += s_sc[s] * __ldg(ep + s * Hn);
                g_ctxT[h][b] = acc;
            }
        }
        gbar();

        // ---------- Phase E: input_feed = tanh(attn_out_w @ [ctx; h1]) ----------
        {
            const float* wr = attn_out_w + (size_t)j * 1024 + kh * 512;
            float a = dot1(wr, kh == 0 ? &g_ctxT[0][0] : &g_h1T[cur][0][0], lane, 512);
            if (kh == 1) part[jl][0][lane] = a;
            __syncthreads();
            if (kh == 0) {
                float f = tanhf(a + part[jl][0][lane]);
                g_feedT[j][lane] = f;
                g_dec[lane * Tn + t][j] = f;
            }
        }
        gbar();
    }
}

// ---------------- FFMA2 helpers (SIMT gemm for out_proj) ----------------
__device__ __forceinline__ unsigned long long pack2(float x)
{ unsigned long long r; asm("mov.b64 %0, {%1, %1};" : "=l"(r) : "f"(x)); return r; }
__device__ __forceinline__ void ffma2(unsigned long long& d, unsigned long long a, unsigned long long b)
{ asm("fma.rn.f32x2 %0, %1, %2, %0;" : "+l"(d) : "l"(a), "l"(b)); }
__device__ __forceinline__ float2 unpack2(unsigned long long v)
{ float2 r; asm("mov.b64 {%0, %1}, %2;" : "=f"(r.x), "=f"(r.y) : "l"(v)); return r; }

__global__ void __launch_bounds__(256)
gemm_nt(const float* __restrict__ A, const float* __restrict__ W,
        const float* __restrict__ bias, float* __restrict__ C,
        int M, int N, int K)
{
    __shared__ __align__(16) float As[16][128];
    __shared__ __align__(16) float Ws[16][128];
    const int m0 = blockIdx.y * 128, n0 = blockIdx.x * 128;
    const int tid = threadIdx.x;
    const int tx = tid & 15, ty = tid >> 4;
    const int lrow = tid >> 1, lcol = (tid & 1) * 8;

    unsigned long long acc2[8][4];
#pragma unroll
    for (int i = 0; i < 8; i++)
#pragma unroll
        for (int jj = 0; jj < 4; jj++) acc2[i][jj] = 0ull;

    const float* Aload = A + (size_t)(m0 + lrow) * K + lcol;
    const float* Wload = W + (size_t)(n0 + lrow) * K + lcol;

    for (int k0 = 0; k0 < K; k0 += 16) {
        float4 a0 = __ldg((const float4*)(Aload + k0));
        float4 a1 = __ldg((const float4*)(Aload + k0 + 4));
        float4 w0 = __ldg((const float4*)(Wload + k0));
        float4 w1 = __ldg((const float4*)(Wload + k0 + 4));
        __syncthreads();
        As[lcol + 0][lrow] = a0.x; As[lcol + 1][lrow] = a0.y;
        As[lcol + 2][lrow] = a0.z; As[lcol + 3][lrow] = a0.w;
        As[lcol + 4][lrow] = a1.x; As[lcol + 5][lrow] = a1.y;
        As[lcol + 6][lrow] = a1.z; As[lcol + 7][lrow] = a1.w;
        Ws[lcol + 0][lrow] = w0.x; Ws[lcol + 1][lrow] = w0.y;
        Ws[lcol + 2][lrow] = w0.z; Ws[lcol + 3][lrow] = w0.w;
        Ws[lcol + 4][lrow] = w1.x; Ws[lcol + 5][lrow] = w1.y;
        Ws[lcol + 6][lrow] = w1.z; Ws[lcol + 7][lrow] = w1.w;
        __syncthreads();
#pragma unroll
        for (int kk = 0; kk < 16; kk++) {
            float4 av0 = *(const float4*)&As[kk][ty * 8];
            float4 av1 = *(const float4*)&As[kk][ty * 8 + 4];
            const ulonglong2* wp = (const ulonglong2*)&Ws[kk][tx * 8];
            ulonglong2 b01 = wp[0], b23 = wp[1];
            float a8[8] = {av0.x, av0.y, av0.z, av0.w, av1.x, av1.y, av1.z, av1.w};
#pragma unroll
            for (int i = 0; i < 8; i++) {
                unsigned long long a2 = pack2(a8[i]);
                ffma2(acc2[i][0], a2, b01.x);
                ffma2(acc2[i][1], a2, b01.y);
                ffma2(acc2[i][2], a2, b23.x);
                ffma2(acc2[i][3], a2, b23.y);
            }
        }
    }
#pragma unroll
    for (int i = 0; i < 8; i++) {
        float* Crow = C + (size_t)(m0 + ty * 8 + i) * N + n0 + tx * 8;
#pragma unroll
        for (int jj = 0; jj < 4; jj++) {
            float2 v = unpack2(acc2[i][jj]);
            if (bias) {
                v.x += __ldg(bias + n0 + tx * 8 + 2 * jj);
                v.y += __ldg(bias + n0 + tx * 8 + 2 * jj + 1);
            }
            *(float2*)(Crow + 2 * jj) = v;
        }
    }
}

// ---------------- fp32 -> bf16 hi/lo split ----------------
__global__ void __launch_bounds__(256)
conv_split(const float4* __restrict__ src, uint2* __restrict__ hi, uint2* __restrict__ lo)
{
    int i = blockIdx.x * 256 + threadIdx.x;
    float4 v = __ldg(src + i);
    __nv_bfloat16 h0 = __float2bfloat16(v.x), h1 = __float2bfloat16(v.y),
                  h2 = __float2bfloat16(v.z), h3 = __float2bfloat16(v.w);
    __nv_bfloat16 l0 = __float2bfloat16(v.x - __bfloat162float(h0));
    __nv_bfloat16 l1 = __float2bfloat16(v.y - __bfloat162float(h1));
    __nv_bfloat16 l2 = __float2bfloat16(v.z - __bfloat162float(h2));
    __nv_bfloat16 l3 = __float2bfloat16(v.w - __bfloat162float(h3));
    uint2 H, L;
    H.x = (uint32_t)__bfloat16_as_ushort(h0) | ((uint32_t)__bfloat16_as_ushort(h1) << 16);
    H.y = (uint32_t)__bfloat16_as_ushort(h2) | ((uint32_t)__bfloat16_as_ushort(h3) << 16);
    L.x = (uint32_t)__bfloat16_as_ushort(l0) | ((uint32_t)__bfloat16_as_ushort(l1) << 16);
    L.y = (uint32_t)__bfloat16_as_ushort(l2) | ((uint32_t)__bfloat16_as_ushort(l3) << 16);
    hi[i] = H; lo[i] = L;
}

// ---------------- mma.sync bf16 3-pass GEMM: C[M,N] = A[M,K] @ B[N,K]^T ----------------
// CTA tile 128x128, 8 warps (2m x 4n), warp tile 64x32, K-chunk 32, double-buffered cp.async.
static constexpr int KC = 32;                 // k per chunk
static constexpr int NCHUNK = En / KC;        // 16
static constexpr int ROWB = 80;               // smem row stride bytes (40 bf16) — conflict-free
static constexpr int MATB = 128 * ROWB;       // 10240 B per matrix
static constexpr int STAGEB = 4 * MATB;       // 40960 B per stage (Ahi,Alo,Bhi,Blo)
static constexpr int GSMEM2 = 2 * STAGEB;     // 81920

__device__ __forceinline__ uint32_t s2u(const void* p)
{
    uint32_t a;
    asm("{ .reg .u64 t; cvta.to.shared.u64 t, %1; cvt.u32.u64 %0, t; }" : "=r"(a) : "l"(p));
    return a;
}
__device__ __forceinline__ void cp16(uint32_t s, const void* g)
{
    asm volatile("cp.async.cg.shared.global [%0], [%1], 16;" :: "r"(s), "l"(g) : "memory");
}
__device__ __forceinline__ void ldmA(uint32_t* r, uint32_t addr)
{
    asm volatile("ldmatrix.sync.aligned.m8n8.x4.shared.b16 {%0,%1,%2,%3}, [%4];"
                 : "=r"(r[0]), "=r"(r[1]), "=r"(r[2]), "=r"(r[3]) : "r"(addr));
}
__device__ __forceinline__ void ldmB(uint32_t* r, uint32_t addr)
{
    asm volatile("ldmatrix.sync.aligned.m8n8.x2.shared.b16 {%0,%1}, [%2];"
                 : "=r"(r[0]), "=r"(r[1]) : "r"(addr));
}
__device__ __forceinline__ void mma16816(float* d, const uint32_t* a, const uint32_t* b)
{
    asm volatile("mma.sync.aligned.m16n8k16.row.col.f32.bf16.bf16.f32 "
                 "{%0,%1,%2,%3}, {%4,%5,%6,%7}, {%8,%9}, {%0,%1,%2,%3};"
                 : "+f"(d[0]), "+f"(d[1]), "+f"(d[2]), "+f"(d[3])
                 : "r"(a[0]), "r"(a[1]), "r"(a[2]), "r"(a[3]), "r"(b[0]), "r"(b[1]));
}

__global__ void __launch_bounds__(256, 1)
gemm_bf16(const __nv_bfloat16* __restrict__ Ahi, const __nv_bfloat16* __restrict__ Alo,
          const __nv_bfloat16* __restrict__ Bhi, const __nv_bfloat16* __restrict__ Blo,
          float* __restrict__ C, int N, int K)
{
    extern __shared__ char smem[];
    const uint32_t su = s2u(smem);
    const int tid = threadIdx.x, wid = tid >> 5, lane = tid & 31;
    const int m0 = blockIdx.x * 128, n0 = blockIdx.y * 128;
    const int wm = wid & 1, wn = wid >> 1;        // warp grid 2(m) x 4(n)

    // loader: this thread's 8 x 16B copies per stage
    const int ci0 = tid;                 // copy ids: tid + 256*r8
    auto load_stage = [&](int chunk) {
        const uint32_t sb = su + (chunk & 1) * STAGEB;
#pragma unroll
        for (int r8 = 0; r8 < 8; r8++) {
            int ci = ci0 + r8 * 256;
            int mat = ci >> 9, rem = ci & 511;
            int row = rem >> 2, seg = rem & 3;
            const __nv_bfloat16* g;
            if (mat == 0)      g = Ahi + (size_t)(m0 + row) * K + chunk * KC + seg * 8;
            else if (mat == 1) g = Alo + (size_t)(m0 + row) * K + chunk * KC + seg * 8;
            else if (mat == 2) g = Bhi + (size_t)(n0 + row) * K + chunk * KC + seg * 8;
            else               g = Blo + (size_t)(n0 + row) * K + chunk * KC + seg * 8;
            cp16(sb + mat * MATB + row * ROWB + seg * 16, g);
        }
        asm volatile("cp.async.commit_group;" ::: "memory");
    };

    float acc[4][4][4];
#pragma unroll
    for (int i = 0; i < 4; i++)
#pragma unroll
        for (int j = 0; j < 4; j++)
#pragma unroll
            for (int k = 0; k < 4; k++) acc[i][j][k] = 0.f;

    load_stage(0);
    load_stage(1);

    for (int c = 0; c < NCHUNK; c++) {
        if (c < NCHUNK - 1) asm volatile("cp.async.wait_group 1;" ::: "memory");
        else                asm volatile("cp.async.wait_group 0;" ::: "memory");
        __syncthreads();
        const uint32_t sb = su + (c & 1) * STAGEB;
        const uint32_t aHiB = sb,            aLoB = sb + MATB;
        const uint32_t bHiB = sb + 2 * MATB, bLoB = sb + 3 * MATB;
#pragma unroll
        for (int ks = 0; ks < 2; ks++) {
            // A fragment addresses: rows wm*64 + mi*16 + (lane&15), k-col ks*16 + (lane>>4)*8
            const uint32_t aoff = (uint32_t)((wm * 64 + (lane & 15)) * ROWB
                                             + (ks * 16 + (lane >> 4) * 8) * 2);
            // B fragment addresses: rows wn*32 + ni*8 + (l&7), k-col ks*16 + (l>>3)*8, l=lane&15
            const int l = lane & 15;
            const uint32_t boff = (uint32_t)((wn * 32 + (l & 7)) * ROWB
                                             + (ks * 16 + (l >> 3) * 8) * 2);
            uint32_t ah[4][4], al[4][4], bh[4][2], bl[4][2];
#pragma unroll
            for (int mi = 0; mi < 4; mi++) {
                ldmA(ah[mi], aHiB + aoff + mi * 16 * ROWB);
                ldmA(al[mi], aLoB + aoff + mi * 16 * ROWB);
            }
#pragma unroll
            for (int ni = 0; ni < 4; ni++) {
                ldmB(bh[ni], bHiB + boff + ni * 8 * ROWB);
                ldmB(bl[ni], bLoB + boff + ni * 8 * ROWB);
            }
#pragma unroll
            for (int mi = 0; mi < 4; mi++)
#pragma unroll
                for (int ni = 0; ni < 4; ni++) {
                    mma16816(acc[mi][ni], ah[mi], bh[ni]);
                    mma16816(acc[mi][ni], ah[mi], bl[ni]);
                    mma16816(acc[mi][ni], al[mi], bh[ni]);
                }
        }
        __syncthreads();
        if (c + 2 < NCHUNK) load_stage(c + 2);
    }

    // epilogue
    const int mbase = m0 + wm * 64 + (lane >> 2);
    const int nbase = n0 + wn * 32 + (lane & 3) * 2;
#pragma unroll
    for (int mi = 0; mi < 4; mi++)
#pragma unroll
        for (int ni = 0; ni < 4; ni++) {
            float* p0 = C + (size_t)(mbase + mi * 16) * N + nbase + ni * 8;
            float* p1 = C + (size_t)(mbase + mi * 16 + 8) * N + nbase + ni * 8;
            *(float2*)p0 = make_float2(acc[mi][ni][0], acc[mi][ni][1]);
            *(float2*)p1 = make_float2(acc[mi][ni][2], acc[mi][ni][3]);
        }
}

extern "C" void kernel_launch(void* const* d_in, const int* in_sizes, int n_in,
                              void* d_out, int out_size)
{
    const int*   tokens     = (const int*)d_in[0];
    const float* enc        = (const float*)d_in[1];
    const int*   mask       = (const int*)d_in[2];
    const float* embed      = (const float*)d_in[3];
    const float* w_ih0      = (const float*)d_in[4];
    const float* w_hh0      = (const float*)d_in[5];
    const float* b_ih0      = (const float*)d_in[6];
    const float* b_hh0      = (const float*)d_in[7];
    const float* w_ih1      = (const float*)d_in[8];
    const float* w_hh1      = (const float*)d_in[9];
    const float* b_ih1      = (const float*)d_in[10];
    const float* b_hh1      = (const float*)d_in[11];
    const float* attn_in_w  = (const float*)d_in[12];
    const float* attn_out_w = (const float*)d_in[13];
    const float* out_proj_w = (const float*)d_in[14];
    const float* out_proj_b = (const float*)d_in[15];
    float* out = (float*)d_out;

    float *dec, *tmp;
    __nv_bfloat16 *Ahi, *Alo, *Bhi, *Blo;
    cudaGetSymbolAddress((void**)&dec, g_dec);
    cudaGetSymbolAddress((void**)&tmp, g_tmp);
    cudaGetSymbolAddress((void**)&Ahi, g_Ahi);
    cudaGetSymbolAddress((void**)&Alo, g_Alo);
    cudaGetSymbolAddress((void**)&Bhi, g_Bhi);
    cudaGetSymbolAddress((void**)&Blo, g_Blo);

    cudaFuncSetAttribute(gemm_bf16, cudaFuncAttributeMaxDynamicSharedMemorySize, GSMEM2);

    // embed hi/lo conversion is independent of the recurrence — issue first
    conv_split<<<Vn * En / 1024, 256>>>((const float4*)embed, (uint2*)Bhi, (uint2*)Blo);
    recurrent_kernel<<<NCTA, NTHR>>>(tokens, enc, mask, embed,
                                     w_ih0, w_hh0, b_ih0, b_hh0,
                                     w_ih1, w_hh1, b_ih1, b_hh1,
                                     attn_in_w, attn_out_w);
    gemm_nt<<<dim3(En / 128, (Bn * Tn) / 128), 256>>>(dec, out_proj_w, out_proj_b, tmp,
                                                      Bn * Tn, En, Hn);
    conv_split<<<Bn * Tn * En / 1024, 256>>>((const float4*)tmp, (uint2*)Ahi, (uint2*)Alo);
    gemm_bf16<<<dim3((Bn * Tn) / 128, Vn / 128), 256, GSMEM2>>>(Ahi, Alo, Bhi, Blo, out, Vn, En);
}

// round 6
// speedup vs baseline: 1.8738x; 1.7217x over previous
#include <cuda_runtime.h>
#include <cuda_bf16.h>
#include <cstdint>

#define NCTA 128
#define NTHR 256
static constexpr int Bn = 32, Tn = 64, Sn = 128, Hn = 512, En = 512, Vn = 32000;
static constexpr float NEGV = -1e4f;

// ---------------- device scratch (allocation-free) ----------------
__device__ __align__(16) float g_xT[Tn][En][Bn];
__device__ __align__(16) float g_feedT[Hn][Bn];
__device__ __align__(16) float g_h0T[2][Hn][Bn];
__device__ __align__(16) float g_h1T[2][Hn][Bn];
__device__ __align__(16) float g_qT[Hn][Bn];
__device__ __align__(16) float g_ctxT[Hn][Bn];
__device__ __align__(16) float g_dec[Bn * Tn][Hn];
__device__ __align__(16) float g_tmp[Bn * Tn][En];
__device__ __nv_bfloat16 g_Ahi[Bn * Tn * En];
__device__ __nv_bfloat16 g_Alo[Bn * Tn * En];
__device__ __nv_bfloat16 g_Bhi[Vn * En];
__device__ __nv_bfloat16 g_Blo[Vn * En];
__device__ unsigned g_count;
__device__ volatile unsigned g_gen;

// ---------------- grid barrier (all 128 CTAs co-resident) ----------------
// __threadfence() is gpu-scope => CCTL.IVALL => L1D flushed, so post-barrier
// __ldca of cross-CTA data is coherent.
__device__ __forceinline__ void gbar()
{
    __threadfence();
    __syncthreads();
    if (threadIdx.x == 0) {
        unsigned g = g_gen;
        unsigned a = atomicAdd(&g_count, 1u);
        if (a == NCTA - 1u) {
            g_count = 0u;
            __threadfence();
            g_gen = g + 1u;
        } else {
            while (g_gen == g) { }
        }
    }
    __syncthreads();
    __threadfence();
}

__device__ __forceinline__ float sigm(float x) { return 1.f / (1.f + __expf(-x)); }

__device__ __forceinline__ unsigned long long pack2(float x)
{ unsigned long long r; asm("mov.b64 %0, {%1, %1};" : "=l"(r) : "f"(x)); return r; }
__device__ __forceinline__ void ffma2(unsigned long long& d, unsigned long long a, unsigned long long b)
{ asm("fma.rn.f32x2 %0, %1, %2, %0;" : "+l"(d) : "l"(a), "l"(b)); }
__device__ __forceinline__ float2 unpack2(unsigned long long v)
{ float2 r; asm("mov.b64 {%0, %1}, %2;" : "=f"(r.x), "=f"(r.y) : "l"(v)); return r; }

// matvec segment: this lane's weight row (wrow already offset to k=0 of segment)
// against activations act[k][32] (q = batch-quad). Accumulates 4 batches into
// two packed f32x2 accumulators. klen % 8 == 0.
__device__ __forceinline__ void mvseg(const float* __restrict__ wrow,
                                      const float* __restrict__ act,
                                      int klen, int q,
                                      unsigned long long& A0, unsigned long long& A1)
{
    const char* ap = (const char*)(act + q * 4);
#pragma unroll 2
    for (int k0 = 0; k0 < klen; k0 += 8) {
        float4 w0 = __ldg((const float4*)(wrow + k0));
        float4 w1 = __ldg((const float4*)(wrow + k0 + 4));
        ulonglong2 av[8];
#pragma unroll
        for (int kk = 0; kk < 8; kk++)
            av[kk] = __ldca((const ulonglong2*)(ap + (size_t)(k0 + kk) * 128));
        float ws[8] = {w0.x, w0.y, w0.z, w0.w, w1.x, w1.y, w1.z, w1.w};
#pragma unroll
        for (int kk = 0; kk < 8; kk++) {
            unsigned long long wp = pack2(ws[kk]);
            ffma2(A0, wp, av[kk].x);
            ffma2(A1, wp, av[kk].y);
        }
    }
}

// ---------------- persistent recurrence ----------------
__global__ void __launch_bounds__(NTHR, 1)
recurrent_kernel(const int* __restrict__ tokens, const float* __restrict__ enc,
                 const int* __restrict__ mask, const float* __restrict__ embed,
                 const float* __restrict__ w_ih0, const float* __restrict__ w_hh0,
                 const float* __restrict__ b_ih0, const float* __restrict__ b_hh0,
                 const float* __restrict__ w_ih1, const float* __restrict__ w_hh1,
                 const float* __restrict__ b_ih1, const float* __restrict__ b_hh1,
                 const float* __restrict__ attn_in_w, const float* __restrict__ attn_out_w)
{
    const int tid = threadIdx.x, cta = blockIdx.x;
    const int warp = tid >> 5, lane = tid & 31;
    const int gtid = cta * NTHR + tid;

    __shared__ __align__(16) float sA[2][4][4][32];   // [kh][g][r][batch]
    __shared__ __align__(16) float s_q[512];
    __shared__ float s_sc[128];
    __shared__ float s_red[32];

    // ---- init recurrent state ----
    for (int i = gtid; i < Hn * Bn; i += NCTA * NTHR) {
        (&g_feedT[0][0])[i] = 0.f;
        (&g_h0T[0][0][0])[i] = 0.f; (&g_h0T[1][0][0])[i] = 0.f;
        (&g_h1T[0][0][0])[i] = 0.f; (&g_h1T[1][0][0])[i] = 0.f;
    }
    // ---- embed gather+transpose ----
    {
        int gw = gtid >> 5;
#pragma unroll
        for (int rep = 0; rep < 2; rep++) {
            int p = gw * 2 + rep;
            int b = p & 31, t0 = p >> 5;
            int tok = __ldg(tokens + b * Tn + t0);
            const float4* er = (const float4*)(embed + (size_t)tok * En);
#pragma unroll
            for (int i = 0; i < 4; i++) {
                float4 v = __ldg(er + i * 32 + lane);
                int e = (i * 32 + lane) * 4;
                g_xT[t0][e][b] = v.x; g_xT[t0][e + 1][b] = v.y;
                g_xT[t0][e + 2][b] = v.z; g_xT[t0][e + 3][b] = v.w;
            }
        }
    }
    gbar();

    // warp roles for matvec phases
    const int g = warp >> 1, kh = warp & 1;
    const int r = lane >> 3, q = lane & 7;
    const int j = cta * 4 + g;          // A/B: j index; C/E: row = cta*4+g

    // gate-row pointers (A/B); row = j + 512*r
    const size_t rowAB = (size_t)(j + 512 * r);
    const float* wih0r = w_ih0 + rowAB * 1024;
    const float* whh0r = w_hh0 + rowAB * 512;
    const float* wih1r = w_ih1 + rowAB * 512;
    const float* whh1r = w_hh1 + rowAB * 512;

    // update-thread state (warps 0-3): (jj, b)
    float c0r = 0.f, c1r = 0.f;
    float biA[4], biB[4];
    if (tid < 128) {
        int jj = tid >> 5, ju = cta * 4 + jj;
#pragma unroll
        for (int rr = 0; rr < 4; rr++) {
            biA[rr] = __ldg(b_ih0 + ju + 512 * rr) + __ldg(b_hh0 + ju + 512 * rr);
            biB[rr] = __ldg(b_ih1 + ju + 512 * rr) + __ldg(b_hh1 + ju + 512 * rr);
        }
    }

    for (int t = 0; t < Tn; t++) {
        const int cur = t & 1, prv = cur ^ 1;

        // ---------- Phase A: LSTM layer 0 gates ----------
        {
            unsigned long long A0 = 0ull, A1 = 0ull;
            if (kh == 0) {
                mvseg(wih0r, &g_xT[t][0][0], 512, q, A0, A1);
                mvseg(wih0r + 512, &g_feedT[0][0], 256, q, A0, A1);
            } else {
                mvseg(wih0r + 768, &g_feedT[256][0], 256, q, A0, A1);
                mvseg(whh0r, &g_h0T[prv][0][0], 512, q, A0, A1);
            }
            float2 v0 = unpack2(A0), v1 = unpack2(A1);
            *(float4*)&sA[kh][g][r][q * 4] = make_float4(v0.x, v0.y, v1.x, v1.y);
            __syncthreads();
            if (tid < 128) {
                int b = tid & 31, jj = tid >> 5;
                float gi = sA[0][jj][0][b] + sA[1][jj][0][b] + biA[0];
                float gf = sA[0][jj][1][b] + sA[1][jj][1][b] + biA[1];
                float gg = sA[0][jj][2][b] + sA[1][jj][2][b] + biA[2];
                float go = sA[0][jj][3][b] + sA[1][jj][3][b] + biA[3];
                c0r = sigm(gf) * c0r + sigm(gi) * tanhf(gg);
                g_h0T[cur][cta * 4 + jj][b] = sigm(go) * tanhf(c0r);
            }
        }
        gbar();

        // ---------- Phase B: LSTM layer 1 gates ----------
        {
            unsigned long long A0 = 0ull, A1 = 0ull;
            if (kh == 0) mvseg(wih1r, &g_h0T[cur][0][0], 512, q, A0, A1);
            else         mvseg(whh1r, &g_h1T[prv][0][0], 512, q, A0, A1);
            float2 v0 = unpack2(A0), v1 = unpack2(A1);
            *(float4*)&sA[kh][g][r][q * 4] = make_float4(v0.x, v0.y, v1.x, v1.y);
            __syncthreads();
            if (tid < 128) {
                int b = tid & 31, jj = tid >> 5;
                float gi = sA[0][jj][0][b] + sA[1][jj][0][b] + biB[0];
                float gf = sA[0][jj][1][b] + sA[1][jj][1][b] + biB[1];
                float gg = sA[0][jj][2][b] + sA[1][jj][2][b] + biB[2];
                float go = sA[0][jj][3][b] + sA[1][jj][3][b] + biB[3];
                c1r = sigm(gf) * c1r + sigm(gi) * tanhf(gg);
                g_h1T[cur][cta * 4 + jj][b] = sigm(go) * tanhf(c1r);
            }
        }
        gbar();

        // ---------- Phase C: q = attn_in_w @ h1 (rows j, K split kh*2 x r*4) ----------
        {
            unsigned long long A0 = 0ull, A1 = 0ull;
            const int ko = kh * 256 + r * 64;
            mvseg(attn_in_w + (size_t)j * 512 + ko, &g_h1T[cur][ko][0], 64, q, A0, A1);
            float2 v0 = unpack2(A0), v1 = unpack2(A1);
            *(float4*)&sA[kh][g][r][q * 4] = make_float4(v0.x, v0.y, v1.x, v1.y);
            __syncthreads();
            if (tid < 128) {
                int b = tid & 31, jj = tid >> 5;
                float s = 0.f;
#pragma unroll
                for (int rr = 0; rr < 4; rr++) s += sA[0][jj][rr][b] + sA[1][jj][rr][b];
                g_qT[cta * 4 + jj][b] = s;
            }
        }
        gbar();

        // ---------- Phase D: scores -> softmax -> ctx (one CTA per batch) ----------
        if (cta < Bn) {
            const int b = cta;
            for (int k = tid; k < 512; k += NTHR) s_q[k] = __ldca(&g_qT[k][b]);
            __syncthreads();
            for (int i = 0; i < 16; i++) {
                int sp = warp * 16 + i;
                const float4* er = (const float4*)(enc + ((size_t)b * Sn + sp) * Hn);
                const float4* qr = (const float4*)s_q;
                float acc = 0.f;
#pragma unroll
                for (int c4 = 0; c4 < 4; c4++) {
                    float4 e = __ldg(er + c4 * 32 + lane);
                    float4 q4 = qr[c4 * 32 + lane];
                    acc += e.x * q4.x + e.y * q4.y + e.z * q4.z + e.w * q4.w;
                }
#pragma unroll
                for (int o = 16; o; o >>= 1) acc += __shfl_xor_sync(~0u, acc, o);
                if (lane == 0)
                    s_sc[sp] = (__ldg(mask + b * Sn + sp) == 0) ? NEGV : acc;
            }
            __syncthreads();
            float mv = (tid < 128) ? s_sc[tid] : -3e38f;
#pragma unroll
            for (int o = 16; o; o >>= 1) mv = fmaxf(mv, __shfl_xor_sync(~0u, mv, o));
            if (lane == 0) s_red[warp] = mv;
            __syncthreads();
            if (tid == 0) {
                float m = s_red[0];
                for (int w = 1; w < 8; w++) m = fmaxf(m, s_red[w]);
                s_red[16] = m;
            }
            __syncthreads();
            float ev = 0.f;
            if (tid < 128) ev = __expf(s_sc[tid] - s_red[16]);
            float sv = ev;
#pragma unroll
            for (int o = 16; o; o >>= 1) sv += __shfl_xor_sync(~0u, sv, o);
            if (lane == 0) s_red[warp] = sv;
            __syncthreads();
            if (tid == 0) {
                float s = 0.f;
                for (int w = 0; w < 8; w++) s += s_red[w];
                s_red[17] = 1.f / s;
            }
            __syncthreads();
            if (tid < 128) s_sc[tid] = ev * s_red[17];
            __syncthreads();
#pragma unroll
            for (int rep = 0; rep < 2; rep++) {
                int h = tid + rep * 256;
                const float* ep = enc + (size_t)b * Sn * Hn + h;
                float acc = 0.f;
#pragma unroll 16
                for (int s = 0; s < Sn; s++) acc += s_sc[s] * __ldg(ep + s * Hn);
                g_ctxT[h][b] = acc;
            }
        }
        gbar();

        // ---------- Phase E: input_feed = tanh(attn_out_w @ [ctx; h1]) ----------
        {
            unsigned long long A0 = 0ull, A1 = 0ull;
            const float* actb = kh ? &g_h1T[cur][r * 128][0] : &g_ctxT[r * 128][0];
            mvseg(attn_out_w + (size_t)j * 1024 + kh * 512 + r * 128, actb, 128, q, A0, A1);
            float2 v0 = unpack2(A0), v1 = unpack2(A1);
            *(float4*)&sA[kh][g][r][q * 4] = make_float4(v0.x, v0.y, v1.x, v1.y);
            __syncthreads();
            if (tid < 128) {
                int b = tid & 31, jj = tid >> 5;
                float s = 0.f;
#pragma unroll
                for (int rr = 0; rr < 4; rr++) s += sA[0][jj][rr][b] + sA[1][jj][rr][b];
                float f = tanhf(s);
                g_feedT[cta * 4 + jj][b] = f;
                g_dec[b * Tn + t][cta * 4 + jj] = f;
            }
        }
        gbar();
    }
}

// ---------------- SIMT f32x2 gemm (out_proj) ----------------
__global__ void __launch_bounds__(256)
gemm_nt(const float* __restrict__ A, const float* __restrict__ W,
        const float* __restrict__ bias, float* __restrict__ C,
        int M, int N, int K)
{
    __shared__ __align__(16) float As[16][128];
    __shared__ __align__(16) float Ws[16][128];
    const int m0 = blockIdx.y * 128, n0 = blockIdx.x * 128;
    const int tid = threadIdx.x;
    const int tx = tid & 15, ty = tid >> 4;
    const int lrow = tid >> 1, lcol = (tid & 1) * 8;

    unsigned long long acc2[8][4];
#pragma unroll
    for (int i = 0; i < 8; i++)
#pragma unroll
        for (int jj = 0; jj < 4; jj++) acc2[i][jj] = 0ull;

    const float* Aload = A + (size_t)(m0 + lrow) * K + lcol;
    const float* Wload = W + (size_t)(n0 + lrow) * K + lcol;

    for (int k0 = 0; k0 < K; k0 += 16) {
        float4 a0 = __ldg((const float4*)(Aload + k0));
        float4 a1 = __ldg((const float4*)(Aload + k0 + 4));
        float4 w0 = __ldg((const float4*)(Wload + k0));
        float4 w1 = __ldg((const float4*)(Wload + k0 + 4));
        __syncthreads();
        As[lcol + 0][lrow] = a0.x; As[lcol + 1][lrow] = a0.y;
        As[lcol + 2][lrow] = a0.z; As[lcol + 3][lrow] = a0.w;
        As[lcol + 4][lrow] = a1.x; As[lcol + 5][lrow] = a1.y;
        As[lcol + 6][lrow] = a1.z; As[lcol + 7][lrow] = a1.w;
        Ws[lcol + 0][lrow] = w0.x; Ws[lcol + 1][lrow] = w0.y;
        Ws[lcol + 2][lrow] = w0.z; Ws[lcol + 3][lrow] = w0.w;
        Ws[lcol + 4][lrow] = w1.x; Ws[lcol + 5][lrow] = w1.y;
        Ws[lcol + 6][lrow] = w1.z; Ws[lcol + 7][lrow] = w1.w;
        __syncthreads();
#pragma unroll
        for (int kk = 0; kk < 16; kk++) {
            float4 av0 = *(const float4*)&As[kk][ty * 8];
            float4 av1 = *(const float4*)&As[kk][ty * 8 + 4];
            const ulonglong2* wp = (const ulonglong2*)&Ws[kk][tx * 8];
            ulonglong2 b01 = wp[0], b23 = wp[1];
            float a8[8] = {av0.x, av0.y, av0.z, av0.w, av1.x, av1.y, av1.z, av1.w};
#pragma unroll
            for (int i = 0; i < 8; i++) {
                unsigned long long a2 = pack2(a8[i]);
                ffma2(acc2[i][0], a2, b01.x);
                ffma2(acc2[i][1], a2, b01.y);
                ffma2(acc2[i][2], a2, b23.x);
                ffma2(acc2[i][3], a2, b23.y);
            }
        }
    }
#pragma unroll
    for (int i = 0; i < 8; i++) {
        float* Crow = C + (size_t)(m0 + ty * 8 + i) * N + n0 + tx * 8;
#pragma unroll
        for (int jj = 0; jj < 4; jj++) {
            float2 v = unpack2(acc2[i][jj]);
            if (bias) {
                v.x += __ldg(bias + n0 + tx * 8 + 2 * jj);
                v.y += __ldg(bias + n0 + tx * 8 + 2 * jj + 1);
            }
            *(float2*)(Crow + 2 * jj) = v;
        }
    }
}

// ---------------- fp32 -> bf16 hi/lo split ----------------
__global__ void __launch_bounds__(256)
conv_split(const float4* __restrict__ src, uint2* __restrict__ hi, uint2* __restrict__ lo)
{
    int i = blockIdx.x * 256 + threadIdx.x;
    float4 v = __ldg(src + i);
    __nv_bfloat16 h0 = __float2bfloat16(v.x), h1 = __float2bfloat16(v.y),
                  h2 = __float2bfloat16(v.z), h3 = __float2bfloat16(v.w);
    __nv_bfloat16 l0 = __float2bfloat16(v.x - __bfloat162float(h0));
    __nv_bfloat16 l1 = __float2bfloat16(v.y - __bfloat162float(h1));
    __nv_bfloat16 l2 = __float2bfloat16(v.z - __bfloat162float(h2));
    __nv_bfloat16 l3 = __float2bfloat16(v.w - __bfloat162float(h3));
    uint2 H, L;
    H.x = (uint32_t)__bfloat16_as_ushort(h0) | ((uint32_t)__bfloat16_as_ushort(h1) << 16);
    H.y = (uint32_t)__bfloat16_as_ushort(h2) | ((uint32_t)__bfloat16_as_ushort(h3) << 16);
    L.x = (uint32_t)__bfloat16_as_ushort(l0) | ((uint32_t)__bfloat16_as_ushort(l1) << 16);
    L.y = (uint32_t)__bfloat16_as_ushort(l2) | ((uint32_t)__bfloat16_as_ushort(l3) << 16);
    hi[i] = H; lo[i] = L;
}

// ---------------- mma.sync bf16 3-pass GEMM: C = A @ B^T ----------------
static constexpr int KC = 32;
static constexpr int NCHUNK = En / KC;
static constexpr int ROWB = 80;
static constexpr int MATB = 128 * ROWB;
static constexpr int STAGEB = 4 * MATB;
static constexpr int GSMEM2 = 2 * STAGEB;

__device__ __forceinline__ uint32_t s2u(const void* p)
{
    uint32_t a;
    asm("{ .reg .u64 t; cvta.to.shared.u64 t, %1; cvt.u32.u64 %0, t; }" : "=r"(a) : "l"(p));
    return a;
}
__device__ __forceinline__ void cp16(uint32_t s, const void* g)
{
    asm volatile("cp.async.cg.shared.global [%0], [%1], 16;" :: "r"(s), "l"(g) : "memory");
}
__device__ __forceinline__ void ldmA(uint32_t* r, uint32_t addr)
{
    asm volatile("ldmatrix.sync.aligned.m8n8.x4.shared.b16 {%0,%1,%2,%3}, [%4];"
                 : "=r"(r[0]), "=r"(r[1]), "=r"(r[2]), "=r"(r[3]) : "r"(addr));
}
__device__ __forceinline__ void ldmB(uint32_t* r, uint32_t addr)
{
    asm volatile("ldmatrix.sync.aligned.m8n8.x2.shared.b16 {%0,%1}, [%2];"
                 : "=r"(r[0]), "=r"(r[1]) : "r"(addr));
}
__device__ __forceinline__ void mma16816(float* d, const uint32_t* a, const uint32_t* b)
{
    asm volatile("mma.sync.aligned.m16n8k16.row.col.f32.bf16.bf16.f32 "
                 "{%0,%1,%2,%3}, {%4,%5,%6,%7}, {%8,%9}, {%0,%1,%2,%3};"
                 : "+f"(d[0]), "+f"(d[1]), "+f"(d[2]), "+f"(d[3])
                 : "r"(a[0]), "r"(a[1]), "r"(a[2]), "r"(a[3]), "r"(b[0]), "r"(b[1]));
}

__global__ void __launch_bounds__(256, 1)
gemm_bf16(const __nv_bfloat16* __restrict__ Ahi, const __nv_bfloat16* __restrict__ Alo,
          const __nv_bfloat16* __restrict__ Bhi, const __nv_bfloat16* __restrict__ Blo,
          float* __restrict__ C, int N, int K)
{
    extern __shared__ char smem[];
    const uint32_t su = s2u(smem);
    const int tid = threadIdx.x, wid = tid >> 5, lane = tid & 31;
    const int m0 = blockIdx.x * 128, n0 = blockIdx.y * 128;
    const int wm = wid & 1, wn = wid >> 1;

    const int ci0 = tid;
    auto load_stage = [&](int chunk) {
        const uint32_t sb = su + (chunk & 1) * STAGEB;
#pragma unroll
        for (int r8 = 0; r8 < 8; r8++) {
            int ci = ci0 + r8 * 256;
            int mat = ci >> 9, rem = ci & 511;
            int row = rem >> 2, seg = rem & 3;
            const __nv_bfloat16* g;
            if (mat == 0)      g = Ahi + (size_t)(m0 + row) * K + chunk * KC + seg * 8;
            else if (mat == 1) g = Alo + (size_t)(m0 + row) * K + chunk * KC + seg * 8;
            else if (mat == 2) g = Bhi + (size_t)(n0 + row) * K + chunk * KC + seg * 8;
            else               g = Blo + (size_t)(n0 + row) * K + chunk * KC + seg * 8;
            cp16(sb + mat * MATB + row * ROWB + seg * 16, g);
        }
        asm volatile("cp.async.commit_group;" ::: "memory");
    };

    float acc[4][4][4];
#pragma unroll
    for (int i = 0; i < 4; i++)
#pragma unroll
        for (int jj = 0; jj < 4; jj++)
#pragma unroll
            for (int k = 0; k < 4; k++) acc[i][jj][k] = 0.f;

    load_stage(0);
    load_stage(1);

    for (int c = 0; c < NCHUNK; c++) {
        if (c < NCHUNK - 1) asm volatile("cp.async.wait_group 1;" ::: "memory");
        else                asm volatile("cp.async.wait_group 0;" ::: "memory");
        __syncthreads();
        const uint32_t sb = su + (c & 1) * STAGEB;
        const uint32_t aHiB = sb,            aLoB = sb + MATB;
        const uint32_t bHiB = sb + 2 * MATB, bLoB = sb + 3 * MATB;
#pragma unroll
        for (int ks = 0; ks < 2; ks++) {
            const uint32_t aoff = (uint32_t)((wm * 64 + (lane & 15)) * ROWB
                                             + (ks * 16 + (lane >> 4) * 8) * 2);
            const int l = lane & 15;
            const uint32_t boff = (uint32_t)((wn * 32 + (l & 7)) * ROWB
                                             + (ks * 16 + (l >> 3) * 8) * 2);
            uint32_t ah[4][4], al[4][4], bh[4][2], bl[4][2];
#pragma unroll
            for (int mi = 0; mi < 4; mi++) {
                ldmA(ah[mi], aHiB + aoff + mi * 16 * ROWB);
                ldmA(al[mi], aLoB + aoff + mi * 16 * ROWB);
            }
#pragma unroll
            for (int ni = 0; ni < 4; ni++) {
                ldmB(bh[ni], bHiB + boff + ni * 8 * ROWB);
                ldmB(bl[ni], bLoB + boff + ni * 8 * ROWB);
            }
#pragma unroll
            for (int mi = 0; mi < 4; mi++)
#pragma unroll
                for (int ni = 0; ni < 4; ni++) {
                    mma16816(acc[mi][ni], ah[mi], bh[ni]);
                    mma16816(acc[mi][ni], ah[mi], bl[ni]);
                    mma16816(acc[mi][ni], al[mi], bh[ni]);
                }
        }
        __syncthreads();
        if (c + 2 < NCHUNK) load_stage(c + 2);
    }

    const int mbase = m0 + wm * 64 + (lane >> 2);
    const int nbase = n0 + wn * 32 + (lane & 3) * 2;
#pragma unroll
    for (int mi = 0; mi < 4; mi++)
#pragma unroll
        for (int ni = 0; ni < 4; ni++) {
            float* p0 = C + (size_t)(mbase + mi * 16) * N + nbase + ni * 8;
            float* p1 = C + (size_t)(mbase + mi * 16 + 8) * N + nbase + ni * 8;
            *(float2*)p0 = make_float2(acc[mi][ni][0], acc[mi][ni][1]);
            *(float2*)p1 = make_float2(acc[mi][ni][2], acc[mi][ni][3]);
        }
}

extern "C" void kernel_launch(void* const* d_in, const int* in_sizes, int n_in,
                              void* d_out, int out_size)
{
    const int*   tokens     = (const int*)d_in[0];
    const float* enc        = (const float*)d_in[1];
    const int*   mask       = (const int*)d_in[2];
    const float* embed      = (const float*)d_in[3];
    const float* w_ih0      = (const float*)d_in[4];
    const float* w_hh0      = (const float*)d_in[5];
    const float* b_ih0      = (const float*)d_in[6];
    const float* b_hh0      = (const float*)d_in[7];
    const float* w_ih1      = (const float*)d_in[8];
    const float* w_hh1      = (const float*)d_in[9];
    const float* b_ih1      = (const float*)d_in[10];
    const float* b_hh1      = (const float*)d_in[11];
    const float* attn_in_w  = (const float*)d_in[12];
    const float* attn_out_w = (const float*)d_in[13];
    const float* out_proj_w = (const float*)d_in[14];
    const float* out_proj_b = (const float*)d_in[15];
    float* out = (float*)d_out;

    float *dec, *tmp;
    __nv_bfloat16 *Ahi, *Alo, *Bhi, *Blo;
    cudaGetSymbolAddress((void**)&dec, g_dec);
    cudaGetSymbolAddress((void**)&tmp, g_tmp);
    cudaGetSymbolAddress((void**)&Ahi, g_Ahi);
    cudaGetSymbolAddress((void**)&Alo, g_Alo);
    cudaGetSymbolAddress((void**)&Bhi, g_Bhi);
    cudaGetSymbolAddress((void**)&Blo, g_Blo);

    cudaFuncSetAttribute(gemm_bf16, cudaFuncAttributeMaxDynamicSharedMemorySize, GSMEM2);

    conv_split<<<Vn * En / 1024, 256>>>((const float4*)embed, (uint2*)Bhi, (uint2*)Blo);
    recurrent_kernel<<<NCTA, NTHR>>>(tokens, enc, mask, embed,
                                     w_ih0, w_hh0, b_ih0, b_hh0,
                                     w_ih1, w_hh1, b_ih1, b_hh1,
                                     attn_in_w, attn_out_w);
    gemm_nt<<<dim3(En / 128, (Bn * Tn) / 128), 256>>>(dec, out_proj_w, out_proj_b, tmp,
                                                      Bn * Tn, En, Hn);
    conv_split<<<Bn * Tn * En / 1024, 256>>>((const float4*)tmp, (uint2*)Ahi, (uint2*)Alo);
    gemm_bf16<<<dim3((Bn * Tn) / 128, Vn / 128), 256, GSMEM2>>>(Ahi, Alo, Bhi, Blo, out, Vn, En);
}

// round 7
// speedup vs baseline: 1.9855x; 1.0596x over previous
#include <cuda_runtime.h>
#include <cuda_bf16.h>
#include <cstdint>

#define NCTA 128
#define NTHR 256
static constexpr int Bn = 32, Tn = 64, Sn = 128, Hn = 512, En = 512, Vn = 32000;
static constexpr float NEGV = -1e4f;

// ---------------- device scratch (allocation-free) ----------------
__device__ __align__(16) float g_xT[Tn][En][Bn];
__device__ __align__(16) float g_feedT[Hn][Bn];
__device__ __align__(16) float g_h0T[2][Hn][Bn];
__device__ __align__(16) float g_h1T[2][Hn][Bn];
__device__ __align__(16) float g_qT[Hn][Bn];
__device__ __align__(16) float g_ctxT[Hn][Bn];
__device__ __align__(16) float g_dec[Bn * Tn][Hn];
__device__ __nv_bfloat16 g_Ahi[Bn * Tn * En];
__device__ __nv_bfloat16 g_Alo[Bn * Tn * En];
__device__ __nv_bfloat16 g_Bhi[Vn * En];
__device__ __nv_bfloat16 g_Blo[Vn * En];
__device__ unsigned g_count;
__device__ volatile unsigned g_gen;

// ---------------- grid barrier (all 128 CTAs co-resident) ----------------
// __threadfence() is gpu-scope => CCTL.IVALL => L1D flushed, so post-barrier
// __ldca of cross-CTA data is coherent.
__device__ __forceinline__ void gbar()
{
    __threadfence();
    __syncthreads();
    if (threadIdx.x == 0) {
        unsigned g = g_gen;
        unsigned a = atomicAdd(&g_count, 1u);
        if (a == NCTA - 1u) {
            g_count = 0u;
            __threadfence();
            g_gen = g + 1u;
        } else {
            while (g_gen == g) { }
        }
    }
    __syncthreads();
    __threadfence();
}

__device__ __forceinline__ float sigm(float x) { return 1.f / (1.f + __expf(-x)); }

__device__ __forceinline__ unsigned long long pack2(float x)
{ unsigned long long r; asm("mov.b64 %0, {%1, %1};" : "=l"(r) : "f"(x)); return r; }
__device__ __forceinline__ void ffma2(unsigned long long& d, unsigned long long a, unsigned long long b)
{ asm("fma.rn.f32x2 %0, %1, %2, %0;" : "+l"(d) : "l"(a), "l"(b)); }
__device__ __forceinline__ float2 unpack2(unsigned long long v)
{ float2 r; asm("mov.b64 {%0, %1}, %2;" : "=f"(r.x), "=f"(r.y) : "l"(v)); return r; }

// matvec segment: lane's weight row vs transposed activations act[k][32];
// q = batch-quad. unroll 4 => ~40 loads in flight to cover L2 latency.
__device__ __forceinline__ void mvseg(const float* __restrict__ wrow,
                                      const float* __restrict__ act,
                                      int klen, int q,
                                      unsigned long long& A0, unsigned long long& A1)
{
    const char* ap = (const char*)(act + q * 4);
#pragma unroll 4
    for (int k0 = 0; k0 < klen; k0 += 8) {
        float4 w0 = __ldg((const float4*)(wrow + k0));
        float4 w1 = __ldg((const float4*)(wrow + k0 + 4));
        ulonglong2 av[8];
#pragma unroll
        for (int kk = 0; kk < 8; kk++)
            av[kk] = __ldca((const ulonglong2*)(ap + (size_t)(k0 + kk) * 128));
        float ws[8] = {w0.x, w0.y, w0.z, w0.w, w1.x, w1.y, w1.z, w1.w};
#pragma unroll
        for (int kk = 0; kk < 8; kk++) {
            unsigned long long wp = pack2(ws[kk]);
            ffma2(A0, wp, av[kk].x);
            ffma2(A1, wp, av[kk].y);
        }
    }
}

// ---------------- persistent recurrence ----------------
__global__ void __launch_bounds__(NTHR, 1)
recurrent_kernel(const int* __restrict__ tokens, const float* __restrict__ enc,
                 const int* __restrict__ mask, const float* __restrict__ embed,
                 const float* __restrict__ w_ih0, const float* __restrict__ w_hh0,
                 const float* __restrict__ b_ih0, const float* __restrict__ b_hh0,
                 const float* __restrict__ w_ih1, const float* __restrict__ w_hh1,
                 const float* __restrict__ b_ih1, const float* __restrict__ b_hh1,
                 const float* __restrict__ attn_in_w, const float* __restrict__ attn_out_w)
{
    const int tid = threadIdx.x, cta = blockIdx.x;
    const int warp = tid >> 5, lane = tid & 31;
    const int gtid = cta * NTHR + tid;

    __shared__ __align__(16) float sA[2][4][4][32];   // [kh][g][r][batch]
    __shared__ __align__(16) float s_q[512];
    __shared__ float s_sc[128];
    __shared__ float s_red[32];

    // ---- init recurrent state ----
    for (int i = gtid; i < Hn * Bn; i += NCTA * NTHR) {
        (&g_feedT[0][0])[i] = 0.f;
        (&g_h0T[0][0][0])[i] = 0.f; (&g_h0T[1][0][0])[i] = 0.f;
        (&g_h1T[0][0][0])[i] = 0.f; (&g_h1T[1][0][0])[i] = 0.f;
    }
    // ---- embed gather+transpose ----
    {
        int gw = gtid >> 5;
#pragma unroll
        for (int rep = 0; rep < 2; rep++) {
            int p = gw * 2 + rep;
            int b = p & 31, t0 = p >> 5;
            int tok = __ldg(tokens + b * Tn + t0);
            const float4* er = (const float4*)(embed + (size_t)tok * En);
#pragma unroll
            for (int i = 0; i < 4; i++) {
                float4 v = __ldg(er + i * 32 + lane);
                int e = (i * 32 + lane) * 4;
                g_xT[t0][e][b] = v.x; g_xT[t0][e + 1][b] = v.y;
                g_xT[t0][e + 2][b] = v.z; g_xT[t0][e + 3][b] = v.w;
            }
        }
    }
    gbar();

    const int g = warp >> 1, kh = warp & 1;
    const int r = lane >> 3, q = lane & 7;
    const int j = cta * 4 + g;

    const size_t rowAB = (size_t)(j + 512 * r);
    const float* wih0r = w_ih0 + rowAB * 1024;
    const float* whh0r = w_hh0 + rowAB * 512;
    const float* wih1r = w_ih1 + rowAB * 512;
    const float* whh1r = w_hh1 + rowAB * 512;

    float c0r = 0.f, c1r = 0.f;
    float biA[4], biB[4];
    if (tid < 128) {
        int jj = tid >> 5, ju = cta * 4 + jj;
#pragma unroll
        for (int rr = 0; rr < 4; rr++) {
            biA[rr] = __ldg(b_ih0 + ju + 512 * rr) + __ldg(b_hh0 + ju + 512 * rr);
            biB[rr] = __ldg(b_ih1 + ju + 512 * rr) + __ldg(b_hh1 + ju + 512 * rr);
        }
    }

    for (int t = 0; t < Tn; t++) {
        const int cur = t & 1, prv = cur ^ 1;

        // ---------- Phase A: LSTM layer 0 gates ----------
        {
            unsigned long long A0 = 0ull, A1 = 0ull;
            if (kh == 0) {
                mvseg(wih0r, &g_xT[t][0][0], 512, q, A0, A1);
                mvseg(wih0r + 512, &g_feedT[0][0], 256, q, A0, A1);
            } else {
                mvseg(wih0r + 768, &g_feedT[256][0], 256, q, A0, A1);
                mvseg(whh0r, &g_h0T[prv][0][0], 512, q, A0, A1);
            }
            float2 v0 = unpack2(A0), v1 = unpack2(A1);
            *(float4*)&sA[kh][g][r][q * 4] = make_float4(v0.x, v0.y, v1.x, v1.y);
            __syncthreads();
            if (tid < 128) {
                int b = tid & 31, jj = tid >> 5;
                float gi = sA[0][jj][0][b] + sA[1][jj][0][b] + biA[0];
                float gf = sA[0][jj][1][b] + sA[1][jj][1][b] + biA[1];
                float gg = sA[0][jj][2][b] + sA[1][jj][2][b] + biA[2];
                float go = sA[0][jj][3][b] + sA[1][jj][3][b] + biA[3];
                c0r = sigm(gf) * c0r + sigm(gi) * tanhf(gg);
                g_h0T[cur][cta * 4 + jj][b] = sigm(go) * tanhf(c0r);
            }
        }
        gbar();

        // ---------- Phase B: LSTM layer 1 gates ----------
        {
            unsigned long long A0 = 0ull, A1 = 0ull;
            if (kh == 0) mvseg(wih1r, &g_h0T[cur][0][0], 512, q, A0, A1);
            else         mvseg(whh1r, &g_h1T[prv][0][0], 512, q, A0, A1);
            float2 v0 = unpack2(A0), v1 = unpack2(A1);
            *(float4*)&sA[kh][g][r][q * 4] = make_float4(v0.x, v0.y, v1.x, v1.y);
            __syncthreads();
            if (tid < 128) {
                int b = tid & 31, jj = tid >> 5;
                float gi = sA[0][jj][0][b] + sA[1][jj][0][b] + biB[0];
                float gf = sA[0][jj][1][b] + sA[1][jj][1][b] + biB[1];
                float gg = sA[0][jj][2][b] + sA[1][jj][2][b] + biB[2];
                float go = sA[0][jj][3][b] + sA[1][jj][3][b] + biB[3];
                c1r = sigm(gf) * c1r + sigm(gi) * tanhf(gg);
                g_h1T[cur][cta * 4 + jj][b] = sigm(go) * tanhf(c1r);
            }
        }
        gbar();

        // ---------- Phase C: q = attn_in_w @ h1 ----------
        {
            unsigned long long A0 = 0ull, A1 = 0ull;
            const int ko = kh * 256 + r * 64;
            mvseg(attn_in_w + (size_t)j * 512 + ko, &g_h1T[cur][ko][0], 64, q, A0, A1);
            float2 v0 = unpack2(A0), v1 = unpack2(A1);
            *(float4*)&sA[kh][g][r][q * 4] = make_float4(v0.x, v0.y, v1.x, v1.y);
            __syncthreads();
            if (tid < 128) {
                int b = tid & 31, jj = tid >> 5;
                float s = 0.f;
#pragma unroll
                for (int rr = 0; rr < 4; rr++) s += sA[0][jj][rr][b] + sA[1][jj][rr][b];
                g_qT[cta * 4 + jj][b] = s;
            }
        }
        gbar();

        // ---------- Phase D: scores -> softmax -> ctx (one CTA per batch) ----------
        if (cta < Bn) {
            const int b = cta;
            for (int k = tid; k < 512; k += NTHR) s_q[k] = __ldca(&g_qT[k][b]);
            __syncthreads();
            for (int i = 0; i < 16; i++) {
                int sp = warp * 16 + i;
                const float4* er = (const float4*)(enc + ((size_t)b * Sn + sp) * Hn);
                const float4* qr = (const float4*)s_q;
                float acc = 0.f;
#pragma unroll
                for (int c4 = 0; c4 < 4; c4++) {
                    float4 e = __ldg(er + c4 * 32 + lane);
                    float4 q4 = qr[c4 * 32 + lane];
                    acc += e.x * q4.x + e.y * q4.y + e.z * q4.z + e.w * q4.w;
                }
#pragma unroll
                for (int o = 16; o; o >>= 1) acc += __shfl_xor_sync(~0u, acc, o);
                if (lane == 0)
                    s_sc[sp] = (__ldg(mask + b * Sn + sp) == 0) ? NEGV : acc;
            }
            __syncthreads();
            float mv = (tid < 128) ? s_sc[tid] : -3e38f;
#pragma unroll
            for (int o = 16; o; o >>= 1) mv = fmaxf(mv, __shfl_xor_sync(~0u, mv, o));
            if (lane == 0) s_red[warp] = mv;
            __syncthreads();
            if (tid == 0) {
                float m = s_red[0];
                for (int w = 1; w < 8; w++) m = fmaxf(m, s_red[w]);
                s_red[16] = m;
            }
            __syncthreads();
            float ev = 0.f;
            if (tid < 128) ev = __expf(s_sc[tid] - s_red[16]);
            float sv = ev;
#pragma unroll
            for (int o = 16; o; o >>= 1) sv += __shfl_xor_sync(~0u, sv, o);
            if (lane == 0) s_red[warp] = sv;
            __syncthreads();
            if (tid == 0) {
                float s = 0.f;
                for (int w = 0; w < 8; w++) s += s_red[w];
                s_red[17] = 1.f / s;
            }
            __syncthreads();
            if (tid < 128) s_sc[tid] = ev * s_red[17];
            __syncthreads();
#pragma unroll
            for (int rep = 0; rep < 2; rep++) {
                int h = tid + rep * 256;
                const float* ep = enc + (size_t)b * Sn * Hn + h;
                float acc = 0.f;
#pragma unroll 16
                for (int s = 0; s < Sn; s++) acc += s_sc[s] * __ldg(ep + s * Hn);
                g_ctxT[h][b] = acc;
            }
        }
        gbar();

        // ---------- Phase E: input_feed = tanh(attn_out_w @ [ctx; h1]) ----------
        {
            unsigned long long A0 = 0ull, A1 = 0ull;
            const float* actb = kh ? &g_h1T[cur][r * 128][0] : &g_ctxT[r * 128][0];
            mvseg(attn_out_w + (size_t)j * 1024 + kh * 512 + r * 128, actb, 128, q, A0, A1);
            float2 v0 = unpack2(A0), v1 = unpack2(A1);
            *(float4*)&sA[kh][g][r][q * 4] = make_float4(v0.x, v0.y, v1.x, v1.y);
            __syncthreads();
            if (tid < 128) {
                int b = tid & 31, jj = tid >> 5;
                float s = 0.f;
#pragma unroll
                for (int rr = 0; rr < 4; rr++) s += sA[0][jj][rr][b] + sA[1][jj][rr][b];
                float f = tanhf(s);
                g_feedT[cta * 4 + jj][b] = f;
                g_dec[b * Tn + t][cta * 4 + jj] = f;
            }
        }
        gbar();
    }
}

// ---------------- SIMT f32x2 gemm (out_proj) -> bf16 hi/lo directly ----------------
__device__ __forceinline__ void split_bf16(float v, __nv_bfloat16& h, __nv_bfloat16& l)
{
    h = __float2bfloat16(v);
    l = __float2bfloat16(v - __bfloat162float(h));
}

__global__ void __launch_bounds__(256)
gemm_nt_split(const float* __restrict__ A, const float* __restrict__ W,
              const float* __restrict__ bias,
              __nv_bfloat16* __restrict__ Chi, __nv_bfloat16* __restrict__ Clo,
              int M, int N, int K)
{
    __shared__ __align__(16) float As[16][128];
    __shared__ __align__(16) float Ws[16][128];
    const int m0 = blockIdx.y * 128, n0 = blockIdx.x * 128;
    const int tid = threadIdx.x;
    const int tx = tid & 15, ty = tid >> 4;
    const int lrow = tid >> 1, lcol = (tid & 1) * 8;

    unsigned long long acc2[8][4];
#pragma unroll
    for (int i = 0; i < 8; i++)
#pragma unroll
        for (int jj = 0; jj < 4; jj++) acc2[i][jj] = 0ull;

    const float* Aload = A + (size_t)(m0 + lrow) * K + lcol;
    const float* Wload = W + (size_t)(n0 + lrow) * K + lcol;

    for (int k0 = 0; k0 < K; k0 += 16) {
        float4 a0 = __ldg((const float4*)(Aload + k0));
        float4 a1 = __ldg((const float4*)(Aload + k0 + 4));
        float4 w0 = __ldg((const float4*)(Wload + k0));
        float4 w1 = __ldg((const float4*)(Wload + k0 + 4));
        __syncthreads();
        As[lcol + 0][lrow] = a0.x; As[lcol + 1][lrow] = a0.y;
        As[lcol + 2][lrow] = a0.z; As[lcol + 3][lrow] = a0.w;
        As[lcol + 4][lrow] = a1.x; As[lcol + 5][lrow] = a1.y;
        As[lcol + 6][lrow] = a1.z; As[lcol + 7][lrow] = a1.w;
        Ws[lcol + 0][lrow] = w0.x; Ws[lcol + 1][lrow] = w0.y;
        Ws[lcol + 2][lrow] = w0.z; Ws[lcol + 3][lrow] = w0.w;
        Ws[lcol + 4][lrow] = w1.x; Ws[lcol + 5][lrow] = w1.y;
        Ws[lcol + 6][lrow] = w1.z; Ws[lcol + 7][lrow] = w1.w;
        __syncthreads();
#pragma unroll
        for (int kk = 0; kk < 16; kk++) {
            float4 av0 = *(const float4*)&As[kk][ty * 8];
            float4 av1 = *(const float4*)&As[kk][ty * 8 + 4];
            const ulonglong2* wp = (const ulonglong2*)&Ws[kk][tx * 8];
            ulonglong2 b01 = wp[0], b23 = wp[1];
            float a8[8] = {av0.x, av0.y, av0.z, av0.w, av1.x, av1.y, av1.z, av1.w};
#pragma unroll
            for (int i = 0; i < 8; i++) {
                unsigned long long a2 = pack2(a8[i]);
                ffma2(acc2[i][0], a2, b01.x);
                ffma2(acc2[i][1], a2, b01.y);
                ffma2(acc2[i][2], a2, b23.x);
                ffma2(acc2[i][3], a2, b23.y);
            }
        }
    }
#pragma unroll
    for (int i = 0; i < 8; i++) {
        size_t rowoff = (size_t)(m0 + ty * 8 + i) * N + n0 + tx * 8;
        ushort4 hs, ls;
        unsigned short tmph[8], tmpl[8];
#pragma unroll
        for (int jj = 0; jj < 4; jj++) {
            float2 v = unpack2(acc2[i][jj]);
            v.x += __ldg(bias + n0 + tx * 8 + 2 * jj);
            v.y += __ldg(bias + n0 + tx * 8 + 2 * jj + 1);
            __nv_bfloat16 h0, l0, h1, l1;
            split_bf16(v.x, h0, l0);
            split_bf16(v.y, h1, l1);
            tmph[2 * jj] = __bfloat16_as_ushort(h0); tmph[2 * jj + 1] = __bfloat16_as_ushort(h1);
            tmpl[2 * jj] = __bfloat16_as_ushort(l0); tmpl[2 * jj + 1] = __bfloat16_as_ushort(l1);
        }
        hs = make_ushort4(tmph[0] | (tmph[1] << 16), 0, 0, 0); // unused; store via uint2 below
        (void)hs; (void)ls;
        uint2 H, L;
        H.x = (uint32_t)tmph[0] | ((uint32_t)tmph[1] << 16);
        H.y = (uint32_t)tmph[2] | ((uint32_t)tmph[3] << 16);
        L.x = (uint32_t)tmpl[0] | ((uint32_t)tmpl[1] << 16);
        L.y = (uint32_t)tmpl[2] | ((uint32_t)tmpl[3] << 16);
        uint2 H2, L2;
        H2.x = (uint32_t)tmph[4] | ((uint32_t)tmph[5] << 16);
        H2.y = (uint32_t)tmph[6] | ((uint32_t)tmph[7] << 16);
        L2.x = (uint32_t)tmpl[4] | ((uint32_t)tmpl[5] << 16);
        L2.y = (uint32_t)tmpl[6] | ((uint32_t)tmpl[7] << 16);
        *(uint2*)(Chi + rowoff) = H;  *(uint2*)(Chi + rowoff + 4) = H2;
        *(uint2*)(Clo + rowoff) = L;  *(uint2*)(Clo + rowoff + 4) = L2;
    }
}

// ---------------- fp32 -> bf16 hi/lo split (for embed) ----------------
__global__ void __launch_bounds__(256)
conv_split(const float4* __restrict__ src, uint2* __restrict__ hi, uint2* __restrict__ lo)
{
    int i = blockIdx.x * 256 + threadIdx.x;
    float4 v = __ldg(src + i);
    __nv_bfloat16 h0, l0, h1, l1, h2, l2, h3, l3;
    split_bf16(v.x, h0, l0); split_bf16(v.y, h1, l1);
    split_bf16(v.z, h2, l2); split_bf16(v.w, h3, l3);
    uint2 H, L;
    H.x = (uint32_t)__bfloat16_as_ushort(h0) | ((uint32_t)__bfloat16_as_ushort(h1) << 16);
    H.y = (uint32_t)__bfloat16_as_ushort(h2) | ((uint32_t)__bfloat16_as_ushort(h3) << 16);
    L.x = (uint32_t)__bfloat16_as_ushort(l0) | ((uint32_t)__bfloat16_as_ushort(l1) << 16);
    L.y = (uint32_t)__bfloat16_as_ushort(l2) | ((uint32_t)__bfloat16_as_ushort(l3) << 16);
    hi[i] = H; lo[i] = L;
}

// ---------------- mma.sync bf16 3-pass GEMM: C = A @ B^T ----------------
static constexpr int KC = 32;
static constexpr int NCHUNK = En / KC;
static constexpr int ROWB = 80;
static constexpr int MATB = 128 * ROWB;
static constexpr int STAGEB = 4 * MATB;
static constexpr int GSMEM2 = 2 * STAGEB;

__device__ __forceinline__ uint32_t s2u(const void* p)
{
    uint32_t a;
    asm("{ .reg .u64 t; cvta.to.shared.u64 t, %1; cvt.u32.u64 %0, t; }" : "=r"(a) : "l"(p));
    return a;
}
__device__ __forceinline__ void cp16(uint32_t s, const void* g)
{
    asm volatile("cp.async.cg.shared.global [%0], [%1], 16;" :: "r"(s), "l"(g) : "memory");
}
__device__ __forceinline__ void ldmA(uint32_t* r, uint32_t addr)
{
    asm volatile("ldmatrix.sync.aligned.m8n8.x4.shared.b16 {%0,%1,%2,%3}, [%4];"
                 : "=r"(r[0]), "=r"(r[1]), "=r"(r[2]), "=r"(r[3]) : "r"(addr));
}
__device__ __forceinline__ void ldmB(uint32_t* r, uint32_t addr)
{
    asm volatile("ldmatrix.sync.aligned.m8n8.x2.shared.b16 {%0,%1}, [%2];"
                 : "=r"(r[0]), "=r"(r[1]) : "r"(addr));
}
__device__ __forceinline__ void mma16816(float* d, const uint32_t* a, const uint32_t* b)
{
    asm volatile("mma.sync.aligned.m16n8k16.row.col.f32.bf16.bf16.f32 "
                 "{%0,%1,%2,%3}, {%4,%5,%6,%7}, {%8,%9}, {%0,%1,%2,%3};"
                 : "+f"(d[0]), "+f"(d[1]), "+f"(d[2]), "+f"(d[3])
                 : "r"(a[0]), "r"(a[1]), "r"(a[2]), "r"(a[3]), "r"(b[0]), "r"(b[1]));
}

__global__ void __launch_bounds__(256, 1)
gemm_bf16(const __nv_bfloat16* __restrict__ Ahi, const __nv_bfloat16* __restrict__ Alo,
          const __nv_bfloat16* __restrict__ Bhi, const __nv_bfloat16* __restrict__ Blo,
          float* __restrict__ C, int N, int K)
{
    extern __shared__ char smem[];
    const uint32_t su = s2u(smem);
    const int tid = threadIdx.x, wid = tid >> 5, lane = tid & 31;
    const int m0 = blockIdx.x * 128, n0 = blockIdx.y * 128;
    const int wm = wid & 1, wn = wid >> 1;

    const int ci0 = tid;
    auto load_stage = [&](int chunk) {
        const uint32_t sb = su + (chunk & 1) * STAGEB;
#pragma unroll
        for (int r8 = 0; r8 < 8; r8++) {
            int ci = ci0 + r8 * 256;
            int mat = ci >> 9, rem = ci & 511;
            int row = rem >> 2, seg = rem & 3;
            const __nv_bfloat16* g;
            if (mat == 0)      g = Ahi + (size_t)(m0 + row) * K + chunk * KC + seg * 8;
            else if (mat == 1) g = Alo + (size_t)(m0 + row) * K + chunk * KC + seg * 8;
            else if (mat == 2) g = Bhi + (size_t)(n0 + row) * K + chunk * KC + seg * 8;
            else               g = Blo + (size_t)(n0 + row) * K + chunk * KC + seg * 8;
            cp16(sb + mat * MATB + row * ROWB + seg * 16, g);
        }
        asm volatile("cp.async.commit_group;" ::: "memory");
    };

    float acc[4][4][4];
#pragma unroll
    for (int i = 0; i < 4; i++)
#pragma unroll
        for (int jj = 0; jj < 4; jj++)
#pragma unroll
            for (int k = 0; k < 4; k++) acc[i][jj][k] = 0.f;

    load_stage(0);
    load_stage(1);

    for (int c = 0; c < NCHUNK; c++) {
        if (c < NCHUNK - 1) asm volatile("cp.async.wait_group 1;" ::: "memory");
        else                asm volatile("cp.async.wait_group 0;" ::: "memory");
        __syncthreads();
        const uint32_t sb = su + (c & 1) * STAGEB;
        const uint32_t aHiB = sb,            aLoB = sb + MATB;
        const uint32_t bHiB = sb + 2 * MATB, bLoB = sb + 3 * MATB;
#pragma unroll
        for (int ks = 0; ks < 2; ks++) {
            const uint32_t aoff = (uint32_t)((wm * 64 + (lane & 15)) * ROWB
                                             + (ks * 16 + (lane >> 4) * 8) * 2);
            const int l = lane & 15;
            const uint32_t boff = (uint32_t)((wn * 32 + (l & 7)) * ROWB
                                             + (ks * 16 + (l >> 3) * 8) * 2);
            uint32_t ah[4][4], al[4][4], bh[4][2], bl[4][2];
#pragma unroll
            for (int mi = 0; mi < 4; mi++) {
                ldmA(ah[mi], aHiB + aoff + mi * 16 * ROWB);
                ldmA(al[mi], aLoB + aoff + mi * 16 * ROWB);
            }
#pragma unroll
            for (int ni = 0; ni < 4; ni++) {
                ldmB(bh[ni], bHiB + boff + ni * 8 * ROWB);
                ldmB(bl[ni], bLoB + boff + ni * 8 * ROWB);
            }
#pragma unroll
            for (int mi = 0; mi < 4; mi++)
#pragma unroll
                for (int ni = 0; ni < 4; ni++) {
                    mma16816(acc[mi][ni], ah[mi], bh[ni]);
                    mma16816(acc[mi][ni], ah[mi], bl[ni]);
                    mma16816(acc[mi][ni], al[mi], bh[ni]);
                }
        }
        __syncthreads();
        if (c + 2 < NCHUNK) load_stage(c + 2);
    }

    const int mbase = m0 + wm * 64 + (lane >> 2);
    const int nbase = n0 + wn * 32 + (lane & 3) * 2;
#pragma unroll
    for (int mi = 0; mi < 4; mi++)
#pragma unroll
        for (int ni = 0; ni < 4; ni++) {
            float* p0 = C + (size_t)(mbase + mi * 16) * N + nbase + ni * 8;
            float* p1 = C + (size_t)(mbase + mi * 16 + 8) * N + nbase + ni * 8;
            *(float2*)p0 = make_float2(acc[mi][ni][0], acc[mi][ni][1]);
            *(float2*)p1 = make_float2(acc[mi][ni][2], acc[mi][ni][3]);
        }
}

extern "C" void kernel_launch(void* const* d_in, const int* in_sizes, int n_in,
                              void* d_out, int out_size)
{
    const int*   tokens     = (const int*)d_in[0];
    const float* enc        = (const float*)d_in[1];
    const int*   mask       = (const int*)d_in[2];
    const float* embed      = (const float*)d_in[3];
    const float* w_ih0      = (const float*)d_in[4];
    const float* w_hh0      = (const float*)d_in[5];
    const float* b_ih0      = (const float*)d_in[6];
    const float* b_hh0      = (const float*)d_in[7];
    const float* w_ih1      = (const float*)d_in[8];
    const float* w_hh1      = (const float*)d_in[9];
    const float* b_ih1      = (const float*)d_in[10];
    const float* b_hh1      = (const float*)d_in[11];
    const float* attn_in_w  = (const float*)d_in[12];
    const float* attn_out_w = (const float*)d_in[13];
    const float* out_proj_w = (const float*)d_in[14];
    const float* out_proj_b = (const float*)d_in[15];
    float* out = (float*)d_out;

    float *dec;
    __nv_bfloat16 *Ahi, *Alo, *Bhi, *Blo;
    cudaGetSymbolAddress((void**)&dec, g_dec);
    cudaGetSymbolAddress((void**)&Ahi, g_Ahi);
    cudaGetSymbolAddress((void**)&Alo, g_Alo);
    cudaGetSymbolAddress((void**)&Bhi, g_Bhi);
    cudaGetSymbolAddress((void**)&Blo, g_Blo);

    cudaFuncSetAttribute(gemm_bf16, cudaFuncAttributeMaxDynamicSharedMemorySize, GSMEM2);

    // side stream for the independent embed hi/lo conversion (overlaps the
    // recurrence). Created once on the first (correctness) call; the capture
    // call only records the fork/join, which is graph-capturable.
    static cudaStream_t s2 = nullptr;
    static cudaEvent_t evA = nullptr, evB = nullptr;
    if (!s2) {
        cudaStreamCreateWithFlags(&s2, cudaStreamNonBlocking);
        cudaEventCreateWithFlags(&evA, cudaEventDisableTiming);
        cudaEventCreateWithFlags(&evB, cudaEventDisableTiming);
    }

    cudaEventRecord(evA, 0);
    cudaStreamWaitEvent(s2, evA, 0);
    conv_split<<<Vn * En / 1024, 256, 0, s2>>>((const float4*)embed, (uint2*)Bhi, (uint2*)Blo);
    cudaEventRecord(evB, s2);

    recurrent_kernel<<<NCTA, NTHR>>>(tokens, enc, mask, embed,
                                     w_ih0, w_hh0, b_ih0, b_hh0,
                                     w_ih1, w_hh1, b_ih1, b_hh1,
                                     attn_in_w, attn_out_w);
    gemm_nt_split<<<dim3(En / 128, (Bn * Tn) / 128), 256>>>(dec, out_proj_w, out_proj_b,
                                                            Ahi, Alo, Bn * Tn, En, Hn);
    cudaStreamWaitEvent(0, evB, 0);
    gemm_bf16<<<dim3((Bn * Tn) / 128, Vn / 128), 256, GSMEM2>>>(Ahi, Alo, Bhi, Blo, out, Vn, En);
}